// round 4
// baseline (speedup 1.0000x reference)
#include <cuda_runtime.h>

#define BATCH 2
#define SEQ   2048
#define DMODEL 1024
#define NHEAD 16
#define DHEAD 64
#define SCALE_INV 0.03125f   // 1/sqrt(1024)

// Scratch for projected Q,K,V (allocation-free rule: __device__ globals)
__device__ float g_Q[BATCH * SEQ * DMODEL];
__device__ float g_K[BATCH * SEQ * DMODEL];
__device__ float g_V[BATCH * SEQ * DMODEL];

// ---- tf32 / mma helpers ----------------------------------------------------
__device__ __forceinline__ unsigned tf32r(float x) {
    unsigned r; asm("cvt.rna.tf32.f32 %0, %1;" : "=r"(r) : "f"(x)); return r;
}
__device__ __forceinline__ void mma8(float* c, const unsigned* a, unsigned b0, unsigned b1) {
    asm volatile(
        "mma.sync.aligned.m16n8k8.row.col.f32.tf32.tf32.f32 "
        "{%0,%1,%2,%3}, {%4,%5,%6,%7}, {%8,%9}, {%0,%1,%2,%3};"
        : "+f"(c[0]), "+f"(c[1]), "+f"(c[2]), "+f"(c[3])
        : "r"(a[0]), "r"(a[1]), "r"(a[2]), "r"(a[3]), "r"(b0), "r"(b1));
}
// ldmatrix x4 (b16 view of tf32 8x4 fragments)
__device__ __forceinline__ void ldsm4(unsigned r[4], unsigned addr) {
    asm volatile("ldmatrix.sync.aligned.m8n8.x4.shared.b16 {%0,%1,%2,%3}, [%4];"
                 : "=r"(r[0]), "=r"(r[1]), "=r"(r[2]), "=r"(r[3]) : "r"(addr) : "memory");
}
__device__ __forceinline__ unsigned s2u(const void* p) {
    return (unsigned)__cvta_generic_to_shared(p);
}

// Swizzles for [*, 64] f32 tiles (float index)
__device__ __forceinline__ int off(int r, int c)  { return r * 64 + (c ^ ((r & 7) << 2)); }
__device__ __forceinline__ int offv(int r, int c) { return r * 64 + (c ^ ((r & 3) << 3)); }

// A-fragment (16x8) LDSM address: matrices (r16,c8),(r16+8,c8),(r16,c8+4),(r16+8,c8+4)
__device__ __forceinline__ unsigned afrag_addr(unsigned base, int lane, int row16, int col8) {
    const int m = lane >> 3, r = lane & 7;
    const int row = row16 + r + ((m & 1) << 3);
    const int col = col8 + ((m >> 1) << 2);
    return base + 4u * ((row << 6) + (col ^ (r << 2)));
}
// B-fragment pair (two n-blocks ntp*16, ntp*16+8 at k-block ks*8)
__device__ __forceinline__ unsigned bfrag_addr(unsigned base, int lane, int ntp, int ks) {
    const int m = lane >> 3, r = lane & 7;
    const int row = (ntp << 4) + ((m >> 1) << 3) + r;
    const int col = (ks << 3) + ((m & 1) << 2);
    return base + 4u * ((row << 6) + (col ^ (r << 2)));
}

// Cooperative tile loads (256 threads), tf32-rounded.
__device__ __forceinline__ void load64(float* S, const float* g, int ldg, int tid) {
    #pragma unroll
    for (int it = 0; it < 4; it++) {
        int i = tid + it * 256, r = i >> 4, c4 = (i & 15) << 2;
        float4 v = *(const float4*)(g + (size_t)r * ldg + c4);
        float4 t = make_float4(__uint_as_float(tf32r(v.x)), __uint_as_float(tf32r(v.y)),
                               __uint_as_float(tf32r(v.z)), __uint_as_float(tf32r(v.w)));
        *(float4*)&S[off(r, c4)] = t;
    }
}
__device__ __forceinline__ void load64v(float* S, const float* g, int ldg, int tid) {
    #pragma unroll
    for (int it = 0; it < 4; it++) {
        int i = tid + it * 256, r = i >> 4, c4 = (i & 15) << 2;
        float4 v = *(const float4*)(g + (size_t)r * ldg + c4);
        float4 t = make_float4(__uint_as_float(tf32r(v.x)), __uint_as_float(tf32r(v.y)),
                               __uint_as_float(tf32r(v.z)), __uint_as_float(tf32r(v.w)));
        *(float4*)&S[offv(r, c4)] = t;
    }
}
__device__ __forceinline__ void load128(float* S, const float* g, int ldg, int tid) {
    #pragma unroll
    for (int it = 0; it < 8; it++) {
        int i = tid + it * 256, r = i >> 4, c4 = (i & 15) << 2;
        float4 v = *(const float4*)(g + (size_t)r * ldg + c4);
        float4 t = make_float4(__uint_as_float(tf32r(v.x)), __uint_as_float(tf32r(v.y)),
                               __uint_as_float(tf32r(v.z)), __uint_as_float(tf32r(v.w)));
        *(float4*)&S[off(r, c4)] = t;
    }
}

// ---------------------------------------------------------------------------
// Projection: Y = X @ W^T. 128x64 tiles, 256 threads (8 warps x 16 rows).
// ---------------------------------------------------------------------------
__global__ __launch_bounds__(256) void proj_kernel(
    const float* __restrict__ X,
    const float* __restrict__ Wq,
    const float* __restrict__ Wk,
    const float* __restrict__ Wv)
{
    __shared__ float sA[128 * 64];
    __shared__ float sB[64 * 64];

    const int bz = blockIdx.z;
    const float* __restrict__ W = (bz == 0) ? Wq : (bz == 1) ? Wk : Wv;
    float* __restrict__ Y = (bz == 0) ? g_Q : (bz == 1) ? g_K : g_V;

    const int rowBase = blockIdx.y * 128;
    const int colBase = blockIdx.x * 64;
    const int tid  = threadIdx.x;
    const int warp = tid >> 5;
    const int lane = tid & 31;
    const unsigned uA = s2u(sA), uB = s2u(sB);

    float c[8][4] = {};

    for (int k0 = 0; k0 < DMODEL; k0 += 64) {
        __syncthreads();
        load128(sA, X + (size_t)rowBase * DMODEL + k0, DMODEL, tid);
        load64 (sB, W + (size_t)colBase * DMODEL + k0, DMODEL, tid);
        __syncthreads();
        #pragma unroll
        for (int ks = 0; ks < 8; ks++) {
            unsigned aa[4];
            ldsm4(aa, afrag_addr(uA, lane, warp * 16, ks * 8));
            #pragma unroll
            for (int ntp = 0; ntp < 4; ntp++) {
                unsigned bb[4];
                ldsm4(bb, bfrag_addr(uB, lane, ntp, ks));
                mma8(c[2 * ntp],     aa, bb[0], bb[1]);
                mma8(c[2 * ntp + 1], aa, bb[2], bb[3]);
            }
        }
    }

    const int g = lane >> 2, t = lane & 3;
    const int r0 = rowBase + warp * 16 + g;
    #pragma unroll
    for (int nt = 0; nt < 8; nt++) {
        const int col = colBase + nt * 8 + 2 * t;
        *(float2*)(Y + (size_t)r0 * DMODEL + col)       = make_float2(c[nt][0], c[nt][1]);
        *(float2*)(Y + (size_t)(r0 + 8) * DMODEL + col) = make_float2(c[nt][2], c[nt][3]);
    }
}

// ---------------------------------------------------------------------------
// Attention per (b,h); head h's q/k/v are CONTIGUOUS [2048,64] matrices.
// 128-query tile, 256 threads (8 warps x 16 rows).
// smem (dynamic, 96KB): sQ[128x64] sK[64x64] sV[64x64] sP[128x64]
// ---------------------------------------------------------------------------
__global__ __launch_bounds__(256) void attn_kernel(
    float* __restrict__ out_attn,   // [B, S, D]
    float* __restrict__ out_sim)    // [B, H, S, S]
{
    extern __shared__ float dyn[];
    float* sQ = dyn;                 // 8192
    float* sK = dyn + 8192;          // 4096
    float* sV = dyn + 12288;         // 4096
    float* sP = dyn + 16384;         // 8192

    const int qt = blockIdx.x;      // 0..15 (128-query tiles)
    const int h  = blockIdx.y;
    const int b  = blockIdx.z;

    const size_t headOff = ((size_t)b * SEQ + (size_t)h * 128) * DMODEL;
    const float* __restrict__ Qh = g_Q + headOff;
    const float* __restrict__ Kh = g_K + headOff;
    const float* __restrict__ Vh = g_V + headOff;
    float* __restrict__ simB = out_sim + (size_t)(b * NHEAD + h) * SEQ * SEQ;

    const int tid  = threadIdx.x;
    const int warp = tid >> 5;
    const int lane = tid & 31;
    const int g = lane >> 2, t = lane & 3;
    const unsigned uQ = s2u(sQ), uK = s2u(sK), uP = s2u(sP);

    load128(sQ, Qh + (size_t)qt * 128 * DHEAD, DHEAD, tid);

    const int rloc = warp * 16 + g;
    const int qrow = qt * 128 + rloc;

    float m0 = -1e30f, m1 = -1e30f, den0 = 0.0f, den1 = 0.0f;

    // ---------------- Phase 1: running max/sum ----------------
    for (int kt = 0; kt < 32; kt++) {
        __syncthreads();
        load64(sK, Kh + (size_t)kt * 64 * DHEAD, DHEAD, tid);
        __syncthreads();

        float c[8][4] = {};
        #pragma unroll
        for (int ks = 0; ks < 8; ks++) {
            unsigned aa[4];
            ldsm4(aa, afrag_addr(uQ, lane, warp * 16, ks * 8));
            #pragma unroll
            for (int ntp = 0; ntp < 4; ntp++) {
                unsigned bb[4];
                ldsm4(bb, bfrag_addr(uK, lane, ntp, ks));
                mma8(c[2 * ntp],     aa, bb[0], bb[1]);
                mma8(c[2 * ntp + 1], aa, bb[2], bb[3]);
            }
        }

        float t0 = -1e30f, t1 = -1e30f;
        #pragma unroll
        for (int nt = 0; nt < 8; nt++) {
            t0 = fmaxf(t0, fmaxf(c[nt][0], c[nt][1]));
            t1 = fmaxf(t1, fmaxf(c[nt][2], c[nt][3]));
        }
        t0 *= SCALE_INV; t1 *= SCALE_INV;
        #pragma unroll
        for (int o = 1; o < 4; o <<= 1) {
            t0 = fmaxf(t0, __shfl_xor_sync(0xffffffffu, t0, o, 4));
            t1 = fmaxf(t1, __shfl_xor_sync(0xffffffffu, t1, o, 4));
        }
        const float n0 = fmaxf(m0, t0), n1 = fmaxf(m1, t1);
        float s0 = 0.0f, s1 = 0.0f;
        #pragma unroll
        for (int nt = 0; nt < 8; nt++) {
            s0 += __expf(c[nt][0] * SCALE_INV - n0) + __expf(c[nt][1] * SCALE_INV - n0);
            s1 += __expf(c[nt][2] * SCALE_INV - n1) + __expf(c[nt][3] * SCALE_INV - n1);
        }
        #pragma unroll
        for (int o = 1; o < 4; o <<= 1) {
            s0 += __shfl_xor_sync(0xffffffffu, s0, o, 4);
            s1 += __shfl_xor_sync(0xffffffffu, s1, o, 4);
        }
        den0 = den0 * __expf(m0 - n0) + s0;  m0 = n0;
        den1 = den1 * __expf(m1 - n1) + s1;  m1 = n1;
    }

    const float inv0 = 1.0f / den0;
    const float inv1 = 1.0f / den1;

    // ---------------- Phase 2: recompute, write probs, O += P@V -------------
    float o2[8][4] = {};
    for (int kt = 0; kt < 32; kt++) {
        __syncthreads();                 // all warps done with sK/sV
        load64 (sK, Kh + (size_t)kt * 64 * DHEAD, DHEAD, tid);
        load64v(sV, Vh + (size_t)kt * 64 * DHEAD, DHEAD, tid);
        __syncthreads();

        float c[8][4] = {};
        #pragma unroll
        for (int ks = 0; ks < 8; ks++) {
            unsigned aa[4];
            ldsm4(aa, afrag_addr(uQ, lane, warp * 16, ks * 8));
            #pragma unroll
            for (int ntp = 0; ntp < 4; ntp++) {
                unsigned bb[4];
                ldsm4(bb, bfrag_addr(uK, lane, ntp, ks));
                mma8(c[2 * ntp],     aa, bb[0], bb[1]);
                mma8(c[2 * ntp + 1], aa, bb[2], bb[3]);
            }
        }

        // probs: gmem sim + warp-local sP staging (tf32)
        #pragma unroll
        for (int nt = 0; nt < 8; nt++) {
            float p0 = __expf(c[nt][0] * SCALE_INV - m0) * inv0;
            float p1 = __expf(c[nt][1] * SCALE_INV - m0) * inv0;
            float p2 = __expf(c[nt][2] * SCALE_INV - m1) * inv1;
            float p3 = __expf(c[nt][3] * SCALE_INV - m1) * inv1;
            const int col = kt * 64 + nt * 8 + 2 * t;
            *(float2*)(simB + (size_t)qrow * SEQ + col)       = make_float2(p0, p1);
            *(float2*)(simB + (size_t)(qrow + 8) * SEQ + col) = make_float2(p2, p3);
            const int lc = nt * 8 + 2 * t;
            *(float2*)&sP[off(rloc, lc)] =
                make_float2(__uint_as_float(tf32r(p0)), __uint_as_float(tf32r(p1)));
            *(float2*)&sP[off(rloc + 8, lc)] =
                make_float2(__uint_as_float(tf32r(p2)), __uint_as_float(tf32r(p3)));
        }
        __syncwarp();                    // warp-local sP hand-off

        // O += P @ V (V B-frags: scalar LDS, conflict-free offv swizzle)
        #pragma unroll
        for (int ks = 0; ks < 8; ks++) {
            unsigned aa[4];
            ldsm4(aa, afrag_addr(uP, lane, warp * 16, ks * 8));
            #pragma unroll
            for (int nt = 0; nt < 8; nt++) {
                unsigned b0 = __float_as_uint(sV[offv(ks * 8 + t,     nt * 8 + g)]);
                unsigned b1 = __float_as_uint(sV[offv(ks * 8 + t + 4, nt * 8 + g)]);
                mma8(o2[nt], aa, b0, b1);
            }
        }
    }

    // Write self_attn with the (0,2,1,3) head transpose.
    #pragma unroll
    for (int nt = 0; nt < 8; nt++) {
        const int dh = h * DHEAD + nt * 8 + 2 * t;
        *(float2*)(out_attn + ((size_t)b * SEQ + qrow) * DMODEL + dh)
            = make_float2(o2[nt][0], o2[nt][1]);
        *(float2*)(out_attn + ((size_t)b * SEQ + qrow + 8) * DMODEL + dh)
            = make_float2(o2[nt][2], o2[nt][3]);
    }
}

// ---------------------------------------------------------------------------
extern "C" void kernel_launch(void* const* d_in, const int* in_sizes, int n_in,
                              void* d_out, int out_size)
{
    const float* seq = (const float*)d_in[0];
    const float* Wq  = (const float*)d_in[1];
    const float* Wk  = (const float*)d_in[2];
    const float* Wv  = (const float*)d_in[3];

    float* out_attn = (float*)d_out;
    float* out_sim  = (float*)d_out + (size_t)BATCH * SEQ * DMODEL;

    proj_kernel<<<dim3(DMODEL / 64, (BATCH * SEQ) / 128, 3), 256>>>(seq, Wq, Wk, Wv);

    static int smem_set = 0;
    if (!smem_set) {
        cudaFuncSetAttribute(attn_kernel, cudaFuncAttributeMaxDynamicSharedMemorySize,
                             96 * 1024);
        smem_set = 1;
    }
    attn_kernel<<<dim3(SEQ / 128, NHEAD, BATCH), 256, 96 * 1024>>>(out_attn, out_sim);
}

// round 5
// speedup vs baseline: 1.3559x; 1.3559x over previous
#include <cuda_runtime.h>

#define BATCH 2
#define SEQ   2048
#define DMODEL 1024
#define NHEAD 16
#define DHEAD 64
#define SCALE_INV 0.03125f   // 1/sqrt(1024)

// Scratch for projected Q,K,V (allocation-free rule: __device__ globals).
// NOTE: proj stores tf32-ROUNDED values here, so attn can cp.async raw bytes.
__device__ float g_Q[BATCH * SEQ * DMODEL];
__device__ float g_K[BATCH * SEQ * DMODEL];
__device__ float g_V[BATCH * SEQ * DMODEL];

// ---- helpers ---------------------------------------------------------------
__device__ __forceinline__ unsigned tf32r(float x) {
    unsigned r; asm("cvt.rna.tf32.f32 %0, %1;" : "=r"(r) : "f"(x)); return r;
}
__device__ __forceinline__ void mma8(float* c, const unsigned* a, unsigned b0, unsigned b1) {
    asm volatile(
        "mma.sync.aligned.m16n8k8.row.col.f32.tf32.tf32.f32 "
        "{%0,%1,%2,%3}, {%4,%5,%6,%7}, {%8,%9}, {%0,%1,%2,%3};"
        : "+f"(c[0]), "+f"(c[1]), "+f"(c[2]), "+f"(c[3])
        : "r"(a[0]), "r"(a[1]), "r"(a[2]), "r"(a[3]), "r"(b0), "r"(b1));
}
__device__ __forceinline__ void ldsm4(unsigned r[4], unsigned addr) {
    asm volatile("ldmatrix.sync.aligned.m8n8.x4.shared.b16 {%0,%1,%2,%3}, [%4];"
                 : "=r"(r[0]), "=r"(r[1]), "=r"(r[2]), "=r"(r[3]) : "r"(addr) : "memory");
}
__device__ __forceinline__ unsigned s2u(const void* p) {
    return (unsigned)__cvta_generic_to_shared(p);
}
__device__ __forceinline__ void cpa16(unsigned dst, const void* src) {
    asm volatile("cp.async.cg.shared.global [%0], [%1], 16;" :: "r"(dst), "l"(src));
}
#define CP_COMMIT() asm volatile("cp.async.commit_group;")
#define CP_WAIT0()  asm volatile("cp.async.wait_group 0;")

// Swizzles for [*, 64] f32 tiles (float index)
__device__ __forceinline__ int off(int r, int c)  { return r * 64 + (c ^ ((r & 7) << 2)); }
__device__ __forceinline__ int offv(int r, int c) { return r * 64 + (c ^ ((r & 3) << 3)); }

// A-fragment (16x8) LDSM address (off swizzle)
__device__ __forceinline__ unsigned afrag_addr(unsigned base, int lane, int row16, int col8) {
    const int m = lane >> 3, r = lane & 7;
    const int row = row16 + r + ((m & 1) << 3);
    const int col = col8 + ((m >> 1) << 2);
    return base + 4u * ((row << 6) + (col ^ (r << 2)));
}
// B-fragment pair (two n-blocks ntp*16, ntp*16+8 at k-block ks*8) (off swizzle)
__device__ __forceinline__ unsigned bfrag_addr(unsigned base, int lane, int ntp, int ks) {
    const int m = lane >> 3, r = lane & 7;
    const int row = (ntp << 4) + ((m >> 1) << 3) + r;
    const int col = (ks << 3) + ((m & 1) << 2);
    return base + 4u * ((row << 6) + (col ^ (r << 2)));
}
__device__ __forceinline__ void rna4(unsigned r[4]) {
    r[0] = tf32r(__uint_as_float(r[0])); r[1] = tf32r(__uint_as_float(r[1]));
    r[2] = tf32r(__uint_as_float(r[2])); r[3] = tf32r(__uint_as_float(r[3]));
}

// cp.async issue of a 64x64 f32 tile from a CONTIGUOUS [*,64] source
__device__ __forceinline__ void cp_tile64(unsigned sbase, const float* g, int tid) {
    #pragma unroll
    for (int it = 0; it < 4; it++) {
        int i = tid + it * 256, r = i >> 4, c4 = (i & 15) << 2;
        cpa16(sbase + 4u * off(r, c4), g + r * 64 + c4);
    }
}
__device__ __forceinline__ void cp_tile64v(unsigned sbase, const float* g, int tid) {
    #pragma unroll
    for (int it = 0; it < 4; it++) {
        int i = tid + it * 256, r = i >> 4, c4 = (i & 15) << 2;
        cpa16(sbase + 4u * offv(r, c4), g + r * 64 + c4);
    }
}

// ---------------------------------------------------------------------------
// Projection: Y = X @ W^T, tf32 mma, cp.async double-buffered mainloop.
// 128x64 tiles, 256 threads. Outputs stored tf32-ROUNDED.
// smem: sA[2]x32KB + sB[2]x16KB = 96KB dynamic.
// ---------------------------------------------------------------------------
__global__ void __launch_bounds__(256, 2) proj_kernel(
    const float* __restrict__ X,
    const float* __restrict__ Wq,
    const float* __restrict__ Wk,
    const float* __restrict__ Wv)
{
    extern __shared__ float dyn[];
    float* sA0 = dyn;            // 8192 floats
    float* sA1 = dyn + 8192;
    float* sB0 = dyn + 16384;    // 4096 floats
    float* sB1 = dyn + 20480;

    const int bz = blockIdx.z;
    const float* __restrict__ W = (bz == 0) ? Wq : (bz == 1) ? Wk : Wv;
    float* __restrict__ Y = (bz == 0) ? g_Q : (bz == 1) ? g_K : g_V;

    const int rowBase = blockIdx.y * 128;
    const int colBase = blockIdx.x * 64;
    const int tid  = threadIdx.x;
    const int warp = tid >> 5;
    const int lane = tid & 31;

    const unsigned uA[2] = { s2u(sA0), s2u(sA1) };
    const unsigned uB[2] = { s2u(sB0), s2u(sB1) };

    // issue tiles for k-chunk ki into buffer bi
    auto issue = [&](int ki, int bi) {
        const int k0 = ki * 64;
        #pragma unroll
        for (int it = 0; it < 8; it++) {
            int i = tid + it * 256, r = i >> 4, c4 = (i & 15) << 2;
            cpa16(uA[bi] + 4u * off(r, c4), X + (size_t)(rowBase + r) * DMODEL + k0 + c4);
        }
        #pragma unroll
        for (int it = 0; it < 4; it++) {
            int i = tid + it * 256, r = i >> 4, c4 = (i & 15) << 2;
            cpa16(uB[bi] + 4u * off(r, c4), W + (size_t)(colBase + r) * DMODEL + k0 + c4);
        }
        CP_COMMIT();
    };

    float c[8][4] = {};

    issue(0, 0);
    for (int ki = 0; ki < 16; ki++) {
        CP_WAIT0();
        __syncthreads();
        if (ki + 1 < 16) issue(ki + 1, (ki + 1) & 1);

        const unsigned ua = uA[ki & 1], ub = uB[ki & 1];
        #pragma unroll
        for (int ks = 0; ks < 8; ks++) {
            unsigned aa[4];
            ldsm4(aa, afrag_addr(ua, lane, warp * 16, ks * 8));
            rna4(aa);
            #pragma unroll
            for (int ntp = 0; ntp < 4; ntp++) {
                unsigned bb[4];
                ldsm4(bb, bfrag_addr(ub, lane, ntp, ks));
                rna4(bb);
                mma8(c[2 * ntp],     aa, bb[0], bb[1]);
                mma8(c[2 * ntp + 1], aa, bb[2], bb[3]);
            }
        }
        __syncthreads();
    }

    // store tf32-ROUNDED outputs
    const int g = lane >> 2, t = lane & 3;
    const int r0 = rowBase + warp * 16 + g;
    #pragma unroll
    for (int nt = 0; nt < 8; nt++) {
        const int col = colBase + nt * 8 + 2 * t;
        float2 lo = make_float2(__uint_as_float(tf32r(c[nt][0])),
                                __uint_as_float(tf32r(c[nt][1])));
        float2 hi = make_float2(__uint_as_float(tf32r(c[nt][2])),
                                __uint_as_float(tf32r(c[nt][3])));
        *(float2*)(Y + (size_t)r0 * DMODEL + col)       = lo;
        *(float2*)(Y + (size_t)(r0 + 8) * DMODEL + col) = hi;
    }
}

// ---------------------------------------------------------------------------
// Attention per (b,h). head h's q/k/v = CONTIGUOUS [2048,64] (pre-rounded).
// 128-query tile, 256 threads. cp.async double-buffered K/V, no sP
// (QK frags repacked to PV A-frags via quad shuffles).
// smem: sQ 32KB + K[2]x16KB + V[2]x16KB = 96KB dynamic.
// ---------------------------------------------------------------------------
__global__ void __launch_bounds__(256, 2) attn_kernel(
    float* __restrict__ out_attn,   // [B, S, D]
    float* __restrict__ out_sim)    // [B, H, S, S]
{
    extern __shared__ float dyn[];
    float* sQ = dyn;                                  // 8192 floats
    const unsigned uQ = s2u(sQ);
    const unsigned uK[2] = { s2u(dyn + 8192),  s2u(dyn + 12288) };
    const unsigned uV[2] = { s2u(dyn + 16384), s2u(dyn + 20480) };
    float* vbuf[2] = { dyn + 16384, dyn + 20480 };

    const int qt = blockIdx.x;      // 0..15
    const int h  = blockIdx.y;
    const int b  = blockIdx.z;

    const size_t headOff = ((size_t)b * SEQ + (size_t)h * 128) * DMODEL;
    const float* __restrict__ Qh = g_Q + headOff;
    const float* __restrict__ Kh = g_K + headOff;
    const float* __restrict__ Vh = g_V + headOff;
    float* __restrict__ simB = out_sim + (size_t)(b * NHEAD + h) * SEQ * SEQ;

    const int tid  = threadIdx.x;
    const int warp = tid >> 5;
    const int lane = tid & 31;
    const int g = lane >> 2, t = lane & 3;

    // Q tile (pre-rounded): plain vector copy into swizzled smem
    #pragma unroll
    for (int it = 0; it < 8; it++) {
        int i = tid + it * 256, r = i >> 4, c4 = (i & 15) << 2;
        *(float4*)&sQ[off(r, c4)] =
            *(const float4*)(Qh + (size_t)(qt * 128 + r) * DHEAD + c4);
    }

    const int rloc = warp * 16 + g;
    const int qrow = qt * 128 + rloc;

    float m0 = -1e30f, m1 = -1e30f, den0 = 0.0f, den1 = 0.0f;

    // ---------------- Phase 1: running max/sum (pipelined) ----------------
    cp_tile64(uK[0], Kh, tid); CP_COMMIT();
    for (int kt = 0; kt < 32; kt++) {
        CP_WAIT0();
        __syncthreads();            // data visible to all warps; also covers sQ
        if (kt + 1 < 32) { cp_tile64(uK[(kt + 1) & 1], Kh + (size_t)(kt + 1) * 4096, tid); CP_COMMIT(); }

        const unsigned uk = uK[kt & 1];
        float c[8][4] = {};
        #pragma unroll
        for (int ks = 0; ks < 8; ks++) {
            unsigned aa[4];
            ldsm4(aa, afrag_addr(uQ, lane, warp * 16, ks * 8));
            #pragma unroll
            for (int ntp = 0; ntp < 4; ntp++) {
                unsigned bb[4];
                ldsm4(bb, bfrag_addr(uk, lane, ntp, ks));
                mma8(c[2 * ntp],     aa, bb[0], bb[1]);
                mma8(c[2 * ntp + 1], aa, bb[2], bb[3]);
            }
        }

        float t0 = -1e30f, t1 = -1e30f;
        #pragma unroll
        for (int nt = 0; nt < 8; nt++) {
            t0 = fmaxf(t0, fmaxf(c[nt][0], c[nt][1]));
            t1 = fmaxf(t1, fmaxf(c[nt][2], c[nt][3]));
        }
        t0 *= SCALE_INV; t1 *= SCALE_INV;
        #pragma unroll
        for (int o = 1; o < 4; o <<= 1) {
            t0 = fmaxf(t0, __shfl_xor_sync(0xffffffffu, t0, o, 4));
            t1 = fmaxf(t1, __shfl_xor_sync(0xffffffffu, t1, o, 4));
        }
        const float n0 = fmaxf(m0, t0), n1 = fmaxf(m1, t1);
        float s0 = 0.0f, s1 = 0.0f;
        #pragma unroll
        for (int nt = 0; nt < 8; nt++) {
            s0 += __expf(c[nt][0] * SCALE_INV - n0) + __expf(c[nt][1] * SCALE_INV - n0);
            s1 += __expf(c[nt][2] * SCALE_INV - n1) + __expf(c[nt][3] * SCALE_INV - n1);
        }
        #pragma unroll
        for (int o = 1; o < 4; o <<= 1) {
            s0 += __shfl_xor_sync(0xffffffffu, s0, o, 4);
            s1 += __shfl_xor_sync(0xffffffffu, s1, o, 4);
        }
        den0 = den0 * __expf(m0 - n0) + s0;  m0 = n0;
        den1 = den1 * __expf(m1 - n1) + s1;  m1 = n1;
    }

    const float inv0 = 1.0f / den0;
    const float inv1 = 1.0f / den1;

    // ---------------- Phase 2: recompute, probs, O += P@V (pipelined) -------
    float o2[8][4] = {};
    cp_tile64 (uK[0], Kh, tid);
    cp_tile64v(uV[0], Vh, tid);
    CP_COMMIT();

    const int srcA = (lane & ~3) | (t >> 1);   // quad lane holding cols {2(t/2), +1}
    const int srcB = srcA + 2;                 // cols +4
    const bool odd = t & 1;

    for (int kt = 0; kt < 32; kt++) {
        CP_WAIT0();
        __syncthreads();
        if (kt + 1 < 32) {
            cp_tile64 (uK[(kt + 1) & 1], Kh + (size_t)(kt + 1) * 4096, tid);
            cp_tile64v(uV[(kt + 1) & 1], Vh + (size_t)(kt + 1) * 4096, tid);
            CP_COMMIT();
        }

        const unsigned uk = uK[kt & 1];
        const float* sV = vbuf[kt & 1];

        float c[8][4] = {};
        #pragma unroll
        for (int ks = 0; ks < 8; ks++) {
            unsigned aa[4];
            ldsm4(aa, afrag_addr(uQ, lane, warp * 16, ks * 8));
            #pragma unroll
            for (int ntp = 0; ntp < 4; ntp++) {
                unsigned bb[4];
                ldsm4(bb, bfrag_addr(uk, lane, ntp, ks));
                mma8(c[2 * ntp],     aa, bb[0], bb[1]);
                mma8(c[2 * ntp + 1], aa, bb[2], bb[3]);
            }
        }

        // probs: write fp32 to sim, keep tf32-rounded in c for repack
        #pragma unroll
        for (int nt = 0; nt < 8; nt++) {
            float p0 = __expf(c[nt][0] * SCALE_INV - m0) * inv0;
            float p1 = __expf(c[nt][1] * SCALE_INV - m0) * inv0;
            float p2 = __expf(c[nt][2] * SCALE_INV - m1) * inv1;
            float p3 = __expf(c[nt][3] * SCALE_INV - m1) * inv1;
            const int col = kt * 64 + nt * 8 + 2 * t;
            *(float2*)(simB + (size_t)qrow * SEQ + col)       = make_float2(p0, p1);
            *(float2*)(simB + (size_t)(qrow + 8) * SEQ + col) = make_float2(p2, p3);
            c[nt][0] = __uint_as_float(tf32r(p0));
            c[nt][1] = __uint_as_float(tf32r(p1));
            c[nt][2] = __uint_as_float(tf32r(p2));
            c[nt][3] = __uint_as_float(tf32r(p3));
        }

        // PV: A-frags from quad shuffles of c; B-frags scalar LDS from V
        #pragma unroll
        for (int ks = 0; ks < 8; ks++) {
            float v0 = __shfl_sync(0xffffffffu, c[ks][0], srcA);
            float v1 = __shfl_sync(0xffffffffu, c[ks][1], srcA);
            float v2 = __shfl_sync(0xffffffffu, c[ks][2], srcA);
            float v3 = __shfl_sync(0xffffffffu, c[ks][3], srcA);
            float w0 = __shfl_sync(0xffffffffu, c[ks][0], srcB);
            float w1 = __shfl_sync(0xffffffffu, c[ks][1], srcB);
            float w2 = __shfl_sync(0xffffffffu, c[ks][2], srcB);
            float w3 = __shfl_sync(0xffffffffu, c[ks][3], srcB);
            unsigned aa[4];
            aa[0] = __float_as_uint(odd ? v1 : v0);   // P[g,    ks*8+t]
            aa[1] = __float_as_uint(odd ? v3 : v2);   // P[g+8,  ks*8+t]
            aa[2] = __float_as_uint(odd ? w1 : w0);   // P[g,    ks*8+t+4]
            aa[3] = __float_as_uint(odd ? w3 : w2);   // P[g+8,  ks*8+t+4]
            #pragma unroll
            for (int nt = 0; nt < 8; nt++) {
                unsigned b0 = __float_as_uint(sV[offv(ks * 8 + t,     nt * 8 + g)]);
                unsigned b1 = __float_as_uint(sV[offv(ks * 8 + t + 4, nt * 8 + g)]);
                mma8(o2[nt], aa, b0, b1);
            }
        }
    }

    // Write self_attn with the (0,2,1,3) head transpose.
    #pragma unroll
    for (int nt = 0; nt < 8; nt++) {
        const int dh = h * DHEAD + nt * 8 + 2 * t;
        *(float2*)(out_attn + ((size_t)b * SEQ + qrow) * DMODEL + dh)
            = make_float2(o2[nt][0], o2[nt][1]);
        *(float2*)(out_attn + ((size_t)b * SEQ + qrow + 8) * DMODEL + dh)
            = make_float2(o2[nt][2], o2[nt][3]);
    }
}

// ---------------------------------------------------------------------------
extern "C" void kernel_launch(void* const* d_in, const int* in_sizes, int n_in,
                              void* d_out, int out_size)
{
    const float* seq = (const float*)d_in[0];
    const float* Wq  = (const float*)d_in[1];
    const float* Wk  = (const float*)d_in[2];
    const float* Wv  = (const float*)d_in[3];

    float* out_attn = (float*)d_out;
    float* out_sim  = (float*)d_out + (size_t)BATCH * SEQ * DMODEL;

    static int attr_set = 0;
    if (!attr_set) {
        cudaFuncSetAttribute(proj_kernel, cudaFuncAttributeMaxDynamicSharedMemorySize, 96 * 1024);
        cudaFuncSetAttribute(attn_kernel, cudaFuncAttributeMaxDynamicSharedMemorySize, 96 * 1024);
        attr_set = 1;
    }

    proj_kernel<<<dim3(DMODEL / 64, (BATCH * SEQ) / 128, 3), 256, 96 * 1024>>>(seq, Wq, Wk, Wv);
    attn_kernel<<<dim3(SEQ / 128, NHEAD, BATCH), 256, 96 * 1024>>>(out_attn, out_sim);
}

// round 6
// speedup vs baseline: 1.4350x; 1.0583x over previous
#include <cuda_runtime.h>

#define BATCH 2
#define SEQ   2048
#define DMODEL 1024
#define NHEAD 16
#define DHEAD 64
#define SCALE_INV 0.03125f   // 1/sqrt(1024)

// Scratch (allocation-free rule: __device__ globals).
// g_X/g_W*: tf32-PRE-ROUNDED copies of inputs.
// g_Q/g_K: tf32-rounded projections, head-contiguous [2048,64] per (b,h).
// g_Vt: V projection stored TRANSPOSED per head: [b,h][dh=64][s'=2048].
__device__ float g_X [BATCH * SEQ * DMODEL];
__device__ float g_Wq[DMODEL * DMODEL];
__device__ float g_Wk[DMODEL * DMODEL];
__device__ float g_Wv[DMODEL * DMODEL];
__device__ float g_Q [BATCH * SEQ * DMODEL];
__device__ float g_K [BATCH * SEQ * DMODEL];
__device__ float g_Vt[BATCH * SEQ * DMODEL];

// ---- helpers ---------------------------------------------------------------
__device__ __forceinline__ unsigned tf32r(float x) {
    unsigned r; asm("cvt.rna.tf32.f32 %0, %1;" : "=r"(r) : "f"(x)); return r;
}
__device__ __forceinline__ void mma8(float* c, const unsigned* a, unsigned b0, unsigned b1) {
    asm volatile(
        "mma.sync.aligned.m16n8k8.row.col.f32.tf32.tf32.f32 "
        "{%0,%1,%2,%3}, {%4,%5,%6,%7}, {%8,%9}, {%0,%1,%2,%3};"
        : "+f"(c[0]), "+f"(c[1]), "+f"(c[2]), "+f"(c[3])
        : "r"(a[0]), "r"(a[1]), "r"(a[2]), "r"(a[3]), "r"(b0), "r"(b1));
}
__device__ __forceinline__ void ldsm4(unsigned r[4], unsigned addr) {
    asm volatile("ldmatrix.sync.aligned.m8n8.x4.shared.b16 {%0,%1,%2,%3}, [%4];"
                 : "=r"(r[0]), "=r"(r[1]), "=r"(r[2]), "=r"(r[3]) : "r"(addr) : "memory");
}
__device__ __forceinline__ unsigned s2u(const void* p) {
    return (unsigned)__cvta_generic_to_shared(p);
}
__device__ __forceinline__ void cpa16(unsigned dst, const void* src) {
    asm volatile("cp.async.cg.shared.global [%0], [%1], 16;" :: "r"(dst), "l"(src));
}
#define CP_COMMIT() asm volatile("cp.async.commit_group;")
#define CP_WAIT0()  asm volatile("cp.async.wait_group 0;")

// XOR swizzle for [*, 64] f32 tiles (float index)
__device__ __forceinline__ int off(int r, int c) { return r * 64 + (c ^ ((r & 7) << 2)); }

// A-fragment (16x8) LDSM address: aa[0]=E[r16+g][c8+t] aa[1]=+8row aa[2]=+4col aa[3]=both
__device__ __forceinline__ unsigned afrag_addr(unsigned base, int lane, int row16, int col8) {
    const int m = lane >> 3, r = lane & 7;
    const int row = row16 + r + ((m & 1) << 3);
    const int col = col8 + ((m >> 1) << 2);
    return base + 4u * ((row << 6) + (col ^ (r << 2)));
}
// B-fragment pair (n-blocks ntp*16, ntp*16+8 at k-chunk ks*8)
__device__ __forceinline__ unsigned bfrag_addr(unsigned base, int lane, int ntp, int ks) {
    const int m = lane >> 3, r = lane & 7;
    const int row = (ntp << 4) + ((m >> 1) << 3) + r;
    const int col = (ks << 3) + ((m & 1) << 2);
    return base + 4u * ((row << 6) + (col ^ (r << 2)));
}

// cp.async of 64x64 / 128x64 f32 tiles from strided gmem into off-swizzled smem
__device__ __forceinline__ void cp_tile64s(unsigned sbase, const float* g, int ldg, int tid) {
    #pragma unroll
    for (int it = 0; it < 4; it++) {
        int i = tid + it * 256, r = i >> 4, c4 = (i & 15) << 2;
        cpa16(sbase + 4u * off(r, c4), g + (size_t)r * ldg + c4);
    }
}
__device__ __forceinline__ void cp_tile128s(unsigned sbase, const float* g, int ldg, int tid) {
    #pragma unroll
    for (int it = 0; it < 8; it++) {
        int i = tid + it * 256, r = i >> 4, c4 = (i & 15) << 2;
        cpa16(sbase + 4u * off(r, c4), g + (size_t)r * ldg + c4);
    }
}

// ---------------------------------------------------------------------------
// One-shot tf32 pre-rounding of X and the three weight matrices.
// ---------------------------------------------------------------------------
__global__ void __launch_bounds__(256) round_kernel(
    const float4* __restrict__ X,  const float4* __restrict__ Wq,
    const float4* __restrict__ Wk, const float4* __restrict__ Wv)
{
    const int i = blockIdx.x * 256 + threadIdx.x;   // over 1,835,008 float4s
    const float4* src; float4* dst; int j;
    if (i < 1048576)      { src = X;  dst = (float4*)g_X;  j = i; }
    else if (i < 1310720) { src = Wq; dst = (float4*)g_Wq; j = i - 1048576; }
    else if (i < 1572864) { src = Wk; dst = (float4*)g_Wk; j = i - 1310720; }
    else                  { src = Wv; dst = (float4*)g_Wv; j = i - 1572864; }
    float4 v = src[j];
    v.x = __uint_as_float(tf32r(v.x)); v.y = __uint_as_float(tf32r(v.y));
    v.z = __uint_as_float(tf32r(v.z)); v.w = __uint_as_float(tf32r(v.w));
    dst[j] = v;
}

// ---------------------------------------------------------------------------
// Projection: Y = X @ W^T (pre-rounded inputs, no cvts in mainloop).
// 128x64 tiles, 256 threads, cp.async double-buffered.
// bz==2 (V) stores head-TRANSPOSED into g_Vt; bz<2 store rounded row-major.
// ---------------------------------------------------------------------------
__global__ void __launch_bounds__(256, 2) proj_kernel(int unused)
{
    extern __shared__ float dyn[];
    const unsigned uA[2] = { s2u(dyn),         s2u(dyn + 8192)  };
    const unsigned uB[2] = { s2u(dyn + 16384), s2u(dyn + 20480) };

    const int bz = blockIdx.z;
    const float* __restrict__ W = (bz == 0) ? g_Wq : (bz == 1) ? g_Wk : g_Wv;

    const int rowBase = blockIdx.y * 128;
    const int colBase = blockIdx.x * 64;
    const int tid  = threadIdx.x;
    const int warp = tid >> 5;
    const int lane = tid & 31;

    auto issue = [&](int ki, int bi) {
        const int k0 = ki * 64;
        #pragma unroll
        for (int it = 0; it < 8; it++) {
            int i = tid + it * 256, r = i >> 4, c4 = (i & 15) << 2;
            cpa16(uA[bi] + 4u * off(r, c4), g_X + (size_t)(rowBase + r) * DMODEL + k0 + c4);
        }
        #pragma unroll
        for (int it = 0; it < 4; it++) {
            int i = tid + it * 256, r = i >> 4, c4 = (i & 15) << 2;
            cpa16(uB[bi] + 4u * off(r, c4), W + (size_t)(colBase + r) * DMODEL + k0 + c4);
        }
        CP_COMMIT();
    };

    float c[8][4] = {};
    issue(0, 0);
    for (int ki = 0; ki < 16; ki++) {
        CP_WAIT0();
        __syncthreads();
        if (ki + 1 < 16) issue(ki + 1, (ki + 1) & 1);
        const unsigned ua = uA[ki & 1], ub = uB[ki & 1];
        #pragma unroll
        for (int ks = 0; ks < 8; ks++) {
            unsigned aa[4];
            ldsm4(aa, afrag_addr(ua, lane, warp * 16, ks * 8));
            #pragma unroll
            for (int ntp = 0; ntp < 4; ntp++) {
                unsigned bb[4];
                ldsm4(bb, bfrag_addr(ub, lane, ntp, ks));
                mma8(c[2 * ntp],     aa, bb[0], bb[1]);
                mma8(c[2 * ntp + 1], aa, bb[2], bb[3]);
            }
        }
        __syncthreads();
    }

    const int g = lane >> 2, t = lane & 3;
    const int r0 = rowBase + warp * 16 + g;

    if (bz < 2) {
        float* __restrict__ Y = (bz == 0) ? g_Q : g_K;
        #pragma unroll
        for (int nt = 0; nt < 8; nt++) {
            const int col = colBase + nt * 8 + 2 * t;
            float2 lo = make_float2(__uint_as_float(tf32r(c[nt][0])),
                                    __uint_as_float(tf32r(c[nt][1])));
            float2 hi = make_float2(__uint_as_float(tf32r(c[nt][2])),
                                    __uint_as_float(tf32r(c[nt][3])));
            *(float2*)(Y + (size_t)r0 * DMODEL + col)       = lo;
            *(float2*)(Y + (size_t)(r0 + 8) * DMODEL + col) = hi;
        }
    } else {
        // V: scatter into g_Vt[b,h][dh][s'].  For this 128-row tile:
        // b = r0>>11, h = (r0>>7)&15, s' = (r0&127)*16 + (colBase>>6), d = nt*8+2t.
        const int b_ = r0 >> 11;
        const int h_ = (r0 >> 7) & 15;
        const int s0 = (r0 & 127) * 16 + (colBase >> 6);
        float* __restrict__ Vt = g_Vt + (size_t)(b_ * NHEAD + h_) * DHEAD * SEQ;
        #pragma unroll
        for (int nt = 0; nt < 8; nt++) {
            const int d = nt * 8 + 2 * t;
            Vt[(size_t)d * SEQ + s0]             = __uint_as_float(tf32r(c[nt][0]));
            Vt[(size_t)(d + 1) * SEQ + s0]       = __uint_as_float(tf32r(c[nt][1]));
            Vt[(size_t)d * SEQ + s0 + 128]       = __uint_as_float(tf32r(c[nt][2]));
            Vt[(size_t)(d + 1) * SEQ + s0 + 128] = __uint_as_float(tf32r(c[nt][3]));
        }
    }
}

// ---------------------------------------------------------------------------
// Attention per (b,h). 128-query tile, 256 threads (8 warps x 16 rows).
// Phase 1: QK^T (Q-frags in regs), exp (no max), write UNNORMALIZED exp to
//          sim, lane-local den accumulation.
// Phase 2: cp.async exp tiles back, normalize in A-frag regs, write
//          normalized sim, O += P@Vt (both operands LDSM).
// smem: 2x(128x64) + 2x(64x64) = 96KB dynamic.
// ---------------------------------------------------------------------------
__global__ void __launch_bounds__(256, 2) attn_kernel(
    float* __restrict__ out_attn,   // [B, S, D]
    float* __restrict__ out_sim)    // [B, H, S, S]
{
    extern __shared__ float dyn[];
    const unsigned uE[2] = { s2u(dyn),         s2u(dyn + 8192)  };
    const unsigned uV[2] = { s2u(dyn + 16384), s2u(dyn + 20480) };

    const int qt = blockIdx.x;      // 0..15
    const int h  = blockIdx.y;
    const int b  = blockIdx.z;

    const size_t headOff = ((size_t)b * SEQ + (size_t)h * 128) * DMODEL;
    const float* __restrict__ Qh  = g_Q + headOff;           // [2048,64]
    const float* __restrict__ Kh  = g_K + headOff;           // [2048,64]
    const float* __restrict__ VtH = g_Vt + (size_t)(b * NHEAD + h) * DHEAD * SEQ; // [64,2048]
    float* __restrict__ simB = out_sim + (size_t)(b * NHEAD + h) * SEQ * SEQ;

    const int tid  = threadIdx.x;
    const int warp = tid >> 5;
    const int lane = tid & 31;
    const int g = lane >> 2, t = lane & 3;

    // ---- Q fragments: stage once, keep in registers -------------------------
    {
        float* sQ = dyn;
        #pragma unroll
        for (int it = 0; it < 8; it++) {
            int i = tid + it * 256, r = i >> 4, c4 = (i & 15) << 2;
            *(float4*)&sQ[off(r, c4)] =
                *(const float4*)(Qh + (size_t)(qt * 128 + r) * DHEAD + c4);
        }
    }
    __syncthreads();
    unsigned qa[8][4];
    #pragma unroll
    for (int ks = 0; ks < 8; ks++)
        ldsm4(qa[ks], afrag_addr(uE[0], lane, warp * 16, ks * 8));
    __syncthreads();

    const int rloc = warp * 16 + g;
    const int qrow = qt * 128 + rloc;

    float den0 = 0.0f, den1 = 0.0f;

    // ---------------- Phase 1 ----------------
    cp_tile64s(uE[0], Kh, 64, tid); CP_COMMIT();
    for (int kt = 0; kt < 32; kt++) {
        CP_WAIT0();
        __syncthreads();
        if (kt + 1 < 32) {
            cp_tile64s(uE[(kt + 1) & 1], Kh + (size_t)(kt + 1) * 4096, 64, tid);
            CP_COMMIT();
        }
        const unsigned uk = uE[kt & 1];

        float c[8][4] = {};
        #pragma unroll
        for (int ks = 0; ks < 8; ks++) {
            #pragma unroll
            for (int ntp = 0; ntp < 4; ntp++) {
                unsigned bb[4];
                ldsm4(bb, bfrag_addr(uk, lane, ntp, ks));
                mma8(c[2 * ntp],     qa[ks], bb[0], bb[1]);
                mma8(c[2 * ntp + 1], qa[ks], bb[2], bb[3]);
            }
        }

        #pragma unroll
        for (int nt = 0; nt < 8; nt++) {
            float e0 = __expf(c[nt][0] * SCALE_INV);
            float e1 = __expf(c[nt][1] * SCALE_INV);
            float e2 = __expf(c[nt][2] * SCALE_INV);
            float e3 = __expf(c[nt][3] * SCALE_INV);
            const int col = kt * 64 + nt * 8 + 2 * t;
            *(float2*)(simB + (size_t)qrow * SEQ + col)       = make_float2(e0, e1);
            *(float2*)(simB + (size_t)(qrow + 8) * SEQ + col) = make_float2(e2, e3);
            den0 += e0 + e1;
            den1 += e2 + e3;
        }
    }
    #pragma unroll
    for (int o = 1; o < 4; o <<= 1) {
        den0 += __shfl_xor_sync(0xffffffffu, den0, o, 4);
        den1 += __shfl_xor_sync(0xffffffffu, den1, o, 4);
    }
    const float inv0 = 1.0f / den0;
    const float inv1 = 1.0f / den1;

    // ---------------- Phase 2 ----------------
    float o2[8][4] = {};
    __syncthreads();
    cp_tile128s(uE[0], simB + (size_t)(qt * 128) * SEQ, SEQ, tid);
    cp_tile64s (uV[0], VtH, SEQ, tid);
    CP_COMMIT();

    for (int kt = 0; kt < 32; kt++) {
        CP_WAIT0();
        __syncthreads();
        if (kt + 1 < 32) {
            cp_tile128s(uE[(kt + 1) & 1], simB + (size_t)(qt * 128) * SEQ + (kt + 1) * 64, SEQ, tid);
            cp_tile64s (uV[(kt + 1) & 1], VtH + (kt + 1) * 64, SEQ, tid);
            CP_COMMIT();
        }
        const unsigned ue = uE[kt & 1], uv = uV[kt & 1];

        #pragma unroll
        for (int ks = 0; ks < 8; ks++) {
            unsigned aa[4];
            ldsm4(aa, afrag_addr(ue, lane, warp * 16, ks * 8));
            // normalize (rows g -> inv0, rows g+8 -> inv1)
            float p0 = __uint_as_float(aa[0]) * inv0;
            float p1 = __uint_as_float(aa[1]) * inv1;
            float p2 = __uint_as_float(aa[2]) * inv0;
            float p3 = __uint_as_float(aa[3]) * inv1;
            // write final normalized sim (overwrites raw exp)
            const int col = kt * 64 + ks * 8 + t;
            simB[(size_t)qrow * SEQ + col]           = p0;
            simB[(size_t)(qrow + 8) * SEQ + col]     = p1;
            simB[(size_t)qrow * SEQ + col + 4]       = p2;
            simB[(size_t)(qrow + 8) * SEQ + col + 4] = p3;
            aa[0] = tf32r(p0); aa[1] = tf32r(p1);
            aa[2] = tf32r(p2); aa[3] = tf32r(p3);
            #pragma unroll
            for (int ntp = 0; ntp < 4; ntp++) {
                unsigned bb[4];
                ldsm4(bb, bfrag_addr(uv, lane, ntp, ks));
                mma8(o2[2 * ntp],     aa, bb[0], bb[1]);
                mma8(o2[2 * ntp + 1], aa, bb[2], bb[3]);
            }
        }
    }

    // Write self_attn with the (0,2,1,3) head transpose.
    #pragma unroll
    for (int nt = 0; nt < 8; nt++) {
        const int dh = h * DHEAD + nt * 8 + 2 * t;
        *(float2*)(out_attn + ((size_t)b * SEQ + qrow) * DMODEL + dh)
            = make_float2(o2[nt][0], o2[nt][1]);
        *(float2*)(out_attn + ((size_t)b * SEQ + qrow + 8) * DMODEL + dh)
            = make_float2(o2[nt][2], o2[nt][3]);
    }
}

// ---------------------------------------------------------------------------
extern "C" void kernel_launch(void* const* d_in, const int* in_sizes, int n_in,
                              void* d_out, int out_size)
{
    const float* seq = (const float*)d_in[0];
    const float* Wq  = (const float*)d_in[1];
    const float* Wk  = (const float*)d_in[2];
    const float* Wv  = (const float*)d_in[3];

    float* out_attn = (float*)d_out;
    float* out_sim  = (float*)d_out + (size_t)BATCH * SEQ * DMODEL;

    static int attr_set = 0;
    if (!attr_set) {
        cudaFuncSetAttribute(proj_kernel, cudaFuncAttributeMaxDynamicSharedMemorySize, 96 * 1024);
        cudaFuncSetAttribute(attn_kernel, cudaFuncAttributeMaxDynamicSharedMemorySize, 96 * 1024);
        attr_set = 1;
    }

    round_kernel<<<7168, 256>>>((const float4*)seq, (const float4*)Wq,
                                (const float4*)Wk,  (const float4*)Wv);
    proj_kernel<<<dim3(DMODEL / 64, (BATCH * SEQ) / 128, 3), 256, 96 * 1024>>>(0);
    attn_kernel<<<dim3(SEQ / 128, NHEAD, BATCH), 256, 96 * 1024>>>(out_attn, out_sim);
}

// round 7
// speedup vs baseline: 1.5770x; 1.0990x over previous
#include <cuda_runtime.h>

#define BATCH 2
#define SEQ   2048
#define DMODEL 1024
#define NHEAD 16
#define DHEAD 64
#define SCALE_INV 0.03125f   // 1/sqrt(1024)

// Scratch (allocation-free rule: __device__ globals).
// g_X/g_W*: tf32-PRE-ROUNDED copies of inputs.
// g_Q/g_K: tf32-rounded projections, head-contiguous [2048,64] per (b,h).
// g_Vt: V projection stored TRANSPOSED per head: [b,h][dh=64][s'=2048].
__device__ float g_X [BATCH * SEQ * DMODEL];
__device__ float g_Wq[DMODEL * DMODEL];
__device__ float g_Wk[DMODEL * DMODEL];
__device__ float g_Wv[DMODEL * DMODEL];
__device__ float g_Q [BATCH * SEQ * DMODEL];
__device__ float g_K [BATCH * SEQ * DMODEL];
__device__ float g_Vt[BATCH * SEQ * DMODEL];

// ---- helpers ---------------------------------------------------------------
__device__ __forceinline__ unsigned tf32r(float x) {
    unsigned r; asm("cvt.rna.tf32.f32 %0, %1;" : "=r"(r) : "f"(x)); return r;
}
__device__ __forceinline__ void mma8(float* c, const unsigned* a, unsigned b0, unsigned b1) {
    asm volatile(
        "mma.sync.aligned.m16n8k8.row.col.f32.tf32.tf32.f32 "
        "{%0,%1,%2,%3}, {%4,%5,%6,%7}, {%8,%9}, {%0,%1,%2,%3};"
        : "+f"(c[0]), "+f"(c[1]), "+f"(c[2]), "+f"(c[3])
        : "r"(a[0]), "r"(a[1]), "r"(a[2]), "r"(a[3]), "r"(b0), "r"(b1));
}
__device__ __forceinline__ void ldsm4(unsigned r[4], unsigned addr) {
    asm volatile("ldmatrix.sync.aligned.m8n8.x4.shared.b16 {%0,%1,%2,%3}, [%4];"
                 : "=r"(r[0]), "=r"(r[1]), "=r"(r[2]), "=r"(r[3]) : "r"(addr) : "memory");
}
__device__ __forceinline__ unsigned s2u(const void* p) {
    return (unsigned)__cvta_generic_to_shared(p);
}
__device__ __forceinline__ void cpa16(unsigned dst, const void* src) {
    asm volatile("cp.async.cg.shared.global [%0], [%1], 16;" :: "r"(dst), "l"(src));
}
#define CP_COMMIT() asm volatile("cp.async.commit_group;")
#define CP_WAIT0()  asm volatile("cp.async.wait_group 0;")

// XOR swizzle for [*, 64] f32 tiles (float index)
__device__ __forceinline__ int off(int r, int c) { return r * 64 + (c ^ ((r & 7) << 2)); }

// A-fragment (16x8) LDSM address
__device__ __forceinline__ unsigned afrag_addr(unsigned base, int lane, int row16, int col8) {
    const int m = lane >> 3, r = lane & 7;
    const int row = row16 + r + ((m & 1) << 3);
    const int col = col8 + ((m >> 1) << 2);
    return base + 4u * ((row << 6) + (col ^ (r << 2)));
}
// B-fragment pair (n-blocks ntp*16, ntp*16+8 at k-chunk ks*8)
__device__ __forceinline__ unsigned bfrag_addr(unsigned base, int lane, int ntp, int ks) {
    const int m = lane >> 3, r = lane & 7;
    const int row = (ntp << 4) + ((m >> 1) << 3) + r;
    const int col = (ks << 3) + ((m & 1) << 2);
    return base + 4u * ((row << 6) + (col ^ (r << 2)));
}

// cp.async of 64x64 / 128x64 f32 tiles from strided gmem into off-swizzled smem
__device__ __forceinline__ void cp_tile64s(unsigned sbase, const float* g, int ldg, int tid) {
    #pragma unroll
    for (int it = 0; it < 4; it++) {
        int i = tid + it * 256, r = i >> 4, c4 = (i & 15) << 2;
        cpa16(sbase + 4u * off(r, c4), g + (size_t)r * ldg + c4);
    }
}
__device__ __forceinline__ void cp_tile128s(unsigned sbase, const float* g, int ldg, int tid) {
    #pragma unroll
    for (int it = 0; it < 8; it++) {
        int i = tid + it * 256, r = i >> 4, c4 = (i & 15) << 2;
        cpa16(sbase + 4u * off(r, c4), g + (size_t)r * ldg + c4);
    }
}

// ---------------------------------------------------------------------------
// One-shot tf32 pre-rounding of X and the three weight matrices.
// ---------------------------------------------------------------------------
__global__ void __launch_bounds__(256) round_kernel(
    const float4* __restrict__ X,  const float4* __restrict__ Wq,
    const float4* __restrict__ Wk, const float4* __restrict__ Wv)
{
    const int i = blockIdx.x * 256 + threadIdx.x;   // over 1,835,008 float4s
    const float4* src; float4* dst; int j;
    if (i < 1048576)      { src = X;  dst = (float4*)g_X;  j = i; }
    else if (i < 1310720) { src = Wq; dst = (float4*)g_Wq; j = i - 1048576; }
    else if (i < 1572864) { src = Wk; dst = (float4*)g_Wk; j = i - 1310720; }
    else                  { src = Wv; dst = (float4*)g_Wv; j = i - 1572864; }
    float4 v = src[j];
    v.x = __uint_as_float(tf32r(v.x)); v.y = __uint_as_float(tf32r(v.y));
    v.z = __uint_as_float(tf32r(v.z)); v.w = __uint_as_float(tf32r(v.w));
    dst[j] = v;
}

// ---------------------------------------------------------------------------
// Projection: Y = X @ W^T (pre-rounded inputs). 128x64 tiles, 256 threads,
// cp.async double-buffered. bz==2 (V) stores head-TRANSPOSED into g_Vt.
// ---------------------------------------------------------------------------
__global__ void __launch_bounds__(256, 2) proj_kernel(int unused)
{
    extern __shared__ float dyn[];
    const unsigned uA[2] = { s2u(dyn),         s2u(dyn + 8192)  };
    const unsigned uB[2] = { s2u(dyn + 16384), s2u(dyn + 20480) };

    const int bz = blockIdx.z;
    const float* __restrict__ W = (bz == 0) ? g_Wq : (bz == 1) ? g_Wk : g_Wv;

    const int rowBase = blockIdx.y * 128;
    const int colBase = blockIdx.x * 64;
    const int tid  = threadIdx.x;
    const int warp = tid >> 5;
    const int lane = tid & 31;

    auto issue = [&](int ki, int bi) {
        const int k0 = ki * 64;
        #pragma unroll
        for (int it = 0; it < 8; it++) {
            int i = tid + it * 256, r = i >> 4, c4 = (i & 15) << 2;
            cpa16(uA[bi] + 4u * off(r, c4), g_X + (size_t)(rowBase + r) * DMODEL + k0 + c4);
        }
        #pragma unroll
        for (int it = 0; it < 4; it++) {
            int i = tid + it * 256, r = i >> 4, c4 = (i & 15) << 2;
            cpa16(uB[bi] + 4u * off(r, c4), W + (size_t)(colBase + r) * DMODEL + k0 + c4);
        }
        CP_COMMIT();
    };

    float c[8][4] = {};
    issue(0, 0);
    for (int ki = 0; ki < 16; ki++) {
        CP_WAIT0();
        __syncthreads();
        if (ki + 1 < 16) issue(ki + 1, (ki + 1) & 1);
        const unsigned ua = uA[ki & 1], ub = uB[ki & 1];
        #pragma unroll
        for (int ks = 0; ks < 8; ks++) {
            unsigned aa[4];
            ldsm4(aa, afrag_addr(ua, lane, warp * 16, ks * 8));
            #pragma unroll
            for (int ntp = 0; ntp < 4; ntp++) {
                unsigned bb[4];
                ldsm4(bb, bfrag_addr(ub, lane, ntp, ks));
                mma8(c[2 * ntp],     aa, bb[0], bb[1]);
                mma8(c[2 * ntp + 1], aa, bb[2], bb[3]);
            }
        }
        __syncthreads();
    }

    const int g = lane >> 2, t = lane & 3;
    const int r0 = rowBase + warp * 16 + g;

    if (bz < 2) {
        float* __restrict__ Y = (bz == 0) ? g_Q : g_K;
        #pragma unroll
        for (int nt = 0; nt < 8; nt++) {
            const int col = colBase + nt * 8 + 2 * t;
            float2 lo = make_float2(__uint_as_float(tf32r(c[nt][0])),
                                    __uint_as_float(tf32r(c[nt][1])));
            float2 hi = make_float2(__uint_as_float(tf32r(c[nt][2])),
                                    __uint_as_float(tf32r(c[nt][3])));
            *(float2*)(Y + (size_t)r0 * DMODEL + col)       = lo;
            *(float2*)(Y + (size_t)(r0 + 8) * DMODEL + col) = hi;
        }
    } else {
        const int b_ = r0 >> 11;
        const int h_ = (r0 >> 7) & 15;
        const int s0 = (r0 & 127) * 16 + (colBase >> 6);
        float* __restrict__ Vt = g_Vt + (size_t)(b_ * NHEAD + h_) * DHEAD * SEQ;
        #pragma unroll
        for (int nt = 0; nt < 8; nt++) {
            const int d = nt * 8 + 2 * t;
            Vt[(size_t)d * SEQ + s0]             = __uint_as_float(tf32r(c[nt][0]));
            Vt[(size_t)(d + 1) * SEQ + s0]       = __uint_as_float(tf32r(c[nt][1]));
            Vt[(size_t)d * SEQ + s0 + 128]       = __uint_as_float(tf32r(c[nt][2]));
            Vt[(size_t)(d + 1) * SEQ + s0 + 128] = __uint_as_float(tf32r(c[nt][3]));
        }
    }
}

// ---------------------------------------------------------------------------
// Attention per (b,h). 128-query tile, 256 threads (8 warps x 16 rows).
// Phase 1: QK^T (Q-frags in regs), write UNNORMALIZED exp to sim, den accum.
// Phase 2: cp.async exp tiles back; PV mma on RAW exp frags (no normalize in
//          the fragment path); cooperative float4 normalize-write of sim from
//          smem using sInv[row]; final O scaled by inv once.
// smem: 2x(128x64) + 2x(64x64) = 96KB dynamic + 512B sInv.
// ---------------------------------------------------------------------------
__global__ void __launch_bounds__(256, 2) attn_kernel(
    float* __restrict__ out_attn,   // [B, S, D]
    float* __restrict__ out_sim)    // [B, H, S, S]
{
    extern __shared__ float dyn[];
    __shared__ float sInv[128];
    const unsigned uE[2] = { s2u(dyn),         s2u(dyn + 8192)  };
    const unsigned uV[2] = { s2u(dyn + 16384), s2u(dyn + 20480) };
    float* ebuf[2] = { dyn, dyn + 8192 };

    const int qt = blockIdx.x;      // 0..15
    const int h  = blockIdx.y;
    const int b  = blockIdx.z;

    const size_t headOff = ((size_t)b * SEQ + (size_t)h * 128) * DMODEL;
    const float* __restrict__ Qh  = g_Q + headOff;           // [2048,64]
    const float* __restrict__ Kh  = g_K + headOff;           // [2048,64]
    const float* __restrict__ VtH = g_Vt + (size_t)(b * NHEAD + h) * DHEAD * SEQ; // [64,2048]
    float* __restrict__ simB = out_sim + (size_t)(b * NHEAD + h) * SEQ * SEQ;

    const int tid  = threadIdx.x;
    const int warp = tid >> 5;
    const int lane = tid & 31;
    const int g = lane >> 2, t = lane & 3;

    // ---- Q fragments: stage once, keep in registers -------------------------
    {
        float* sQ = dyn;
        #pragma unroll
        for (int it = 0; it < 8; it++) {
            int i = tid + it * 256, r = i >> 4, c4 = (i & 15) << 2;
            *(float4*)&sQ[off(r, c4)] =
                *(const float4*)(Qh + (size_t)(qt * 128 + r) * DHEAD + c4);
        }
    }
    __syncthreads();
    unsigned qa[8][4];
    #pragma unroll
    for (int ks = 0; ks < 8; ks++)
        ldsm4(qa[ks], afrag_addr(uE[0], lane, warp * 16, ks * 8));
    __syncthreads();

    const int rloc = warp * 16 + g;
    const int qrow = qt * 128 + rloc;

    float den0 = 0.0f, den1 = 0.0f;

    // ---------------- Phase 1 ----------------
    cp_tile64s(uE[0], Kh, 64, tid); CP_COMMIT();
    for (int kt = 0; kt < 32; kt++) {
        CP_WAIT0();
        __syncthreads();
        if (kt + 1 < 32) {
            cp_tile64s(uE[(kt + 1) & 1], Kh + (size_t)(kt + 1) * 4096, 64, tid);
            CP_COMMIT();
        }
        const unsigned uk = uE[kt & 1];

        float c[8][4] = {};
        #pragma unroll
        for (int ks = 0; ks < 8; ks++) {
            #pragma unroll
            for (int ntp = 0; ntp < 4; ntp++) {
                unsigned bb[4];
                ldsm4(bb, bfrag_addr(uk, lane, ntp, ks));
                mma8(c[2 * ntp],     qa[ks], bb[0], bb[1]);
                mma8(c[2 * ntp + 1], qa[ks], bb[2], bb[3]);
            }
        }

        #pragma unroll
        for (int nt = 0; nt < 8; nt++) {
            float e0 = __expf(c[nt][0] * SCALE_INV);
            float e1 = __expf(c[nt][1] * SCALE_INV);
            float e2 = __expf(c[nt][2] * SCALE_INV);
            float e3 = __expf(c[nt][3] * SCALE_INV);
            const int col = kt * 64 + nt * 8 + 2 * t;
            *(float2*)(simB + (size_t)qrow * SEQ + col)       = make_float2(e0, e1);
            *(float2*)(simB + (size_t)(qrow + 8) * SEQ + col) = make_float2(e2, e3);
            den0 += e0 + e1;
            den1 += e2 + e3;
        }
    }
    #pragma unroll
    for (int o = 1; o < 4; o <<= 1) {
        den0 += __shfl_xor_sync(0xffffffffu, den0, o, 4);
        den1 += __shfl_xor_sync(0xffffffffu, den1, o, 4);
    }
    const float inv0 = 1.0f / den0;
    const float inv1 = 1.0f / den1;
    if (t == 0) { sInv[rloc] = inv0; sInv[rloc + 8] = inv1; }

    // ---------------- Phase 2 ----------------
    float o2[8][4] = {};
    __syncthreads();                 // sInv visible; phase-1 smem reads done
    cp_tile128s(uE[0], simB + (size_t)(qt * 128) * SEQ, SEQ, tid);
    cp_tile64s (uV[0], VtH, SEQ, tid);
    CP_COMMIT();

    for (int kt = 0; kt < 32; kt++) {
        CP_WAIT0();
        __syncthreads();
        if (kt + 1 < 32) {
            cp_tile128s(uE[(kt + 1) & 1], simB + (size_t)(qt * 128) * SEQ + (kt + 1) * 64, SEQ, tid);
            cp_tile64s (uV[(kt + 1) & 1], VtH + (kt + 1) * 64, SEQ, tid);
            CP_COMMIT();
        }
        const unsigned ue = uE[kt & 1], uv = uV[kt & 1];

        // PV mma on RAW exp fragments (tf32 truncation in HW)
        #pragma unroll
        for (int ks = 0; ks < 8; ks++) {
            unsigned aa[4];
            ldsm4(aa, afrag_addr(ue, lane, warp * 16, ks * 8));
            #pragma unroll
            for (int ntp = 0; ntp < 4; ntp++) {
                unsigned bb[4];
                ldsm4(bb, bfrag_addr(uv, lane, ntp, ks));
                mma8(o2[2 * ntp],     aa, bb[0], bb[1]);
                mma8(o2[2 * ntp + 1], aa, bb[2], bb[3]);
            }
        }

        // Cooperative normalize of this tile: smem exp -> simB (float4, coalesced)
        const float* eb = ebuf[kt & 1];
        #pragma unroll
        for (int it = 0; it < 8; it++) {
            int i = tid + it * 256, r = i >> 4, c4 = (i & 15) << 2;
            float4 v = *(const float4*)&eb[off(r, c4)];
            const float s = sInv[r];
            v.x *= s; v.y *= s; v.z *= s; v.w *= s;
            *(float4*)(simB + (size_t)(qt * 128 + r) * SEQ + kt * 64 + c4) = v;
        }
    }

    // Write self_attn with the (0,2,1,3) head transpose; scale by inv here.
    #pragma unroll
    for (int nt = 0; nt < 8; nt++) {
        const int dh = h * DHEAD + nt * 8 + 2 * t;
        *(float2*)(out_attn + ((size_t)b * SEQ + qrow) * DMODEL + dh)
            = make_float2(o2[nt][0] * inv0, o2[nt][1] * inv0);
        *(float2*)(out_attn + ((size_t)b * SEQ + qrow + 8) * DMODEL + dh)
            = make_float2(o2[nt][2] * inv1, o2[nt][3] * inv1);
    }
}

// ---------------------------------------------------------------------------
extern "C" void kernel_launch(void* const* d_in, const int* in_sizes, int n_in,
                              void* d_out, int out_size)
{
    const float* seq = (const float*)d_in[0];
    const float* Wq  = (const float*)d_in[1];
    const float* Wk  = (const float*)d_in[2];
    const float* Wv  = (const float*)d_in[3];

    float* out_attn = (float*)d_out;
    float* out_sim  = (float*)d_out + (size_t)BATCH * SEQ * DMODEL;

    static int attr_set = 0;
    if (!attr_set) {
        cudaFuncSetAttribute(proj_kernel, cudaFuncAttributeMaxDynamicSharedMemorySize, 96 * 1024);
        cudaFuncSetAttribute(attn_kernel, cudaFuncAttributeMaxDynamicSharedMemorySize, 96 * 1024);
        attr_set = 1;
    }

    round_kernel<<<7168, 256>>>((const float4*)seq, (const float4*)Wq,
                                (const float4*)Wk,  (const float4*)Wv);
    proj_kernel<<<dim3(DMODEL / 64, (BATCH * SEQ) / 128, 3), 256, 96 * 1024>>>(0);
    attn_kernel<<<dim3(SEQ / 128, NHEAD, BATCH), 256, 96 * 1024>>>(out_attn, out_sim);
}

// round 8
// speedup vs baseline: 1.8088x; 1.1470x over previous
#include <cuda_runtime.h>
#include <cuda_fp16.h>

#define BATCH 2
#define SEQ   2048
#define DMODEL 1024
#define NHEAD 16
#define DHEAD 64
#define SCALE_INV 0.03125f   // 1/sqrt(1024)

// Scratch (allocation-free rule: __device__ globals).
__device__ float  g_X [BATCH * SEQ * DMODEL];
__device__ float  g_Wq[DMODEL * DMODEL];
__device__ float  g_Wk[DMODEL * DMODEL];
__device__ float  g_Wv[DMODEL * DMODEL];
__device__ float  g_Q [BATCH * SEQ * DMODEL];   // tf32-rounded
__device__ float  g_K [BATCH * SEQ * DMODEL];   // tf32-rounded
__device__ __half g_Vt[BATCH * SEQ * DMODEL];   // V^T per head [b,h][dh][s'], fp16
__device__ __half g_E [(size_t)BATCH * NHEAD * SEQ * SEQ];  // raw exp, fp16 (256MB)

// ---- helpers ---------------------------------------------------------------
__device__ __forceinline__ unsigned tf32r(float x) {
    unsigned r; asm("cvt.rna.tf32.f32 %0, %1;" : "=r"(r) : "f"(x)); return r;
}
__device__ __forceinline__ void mma8(float* c, const unsigned* a, unsigned b0, unsigned b1) {
    asm volatile(
        "mma.sync.aligned.m16n8k8.row.col.f32.tf32.tf32.f32 "
        "{%0,%1,%2,%3}, {%4,%5,%6,%7}, {%8,%9}, {%0,%1,%2,%3};"
        : "+f"(c[0]), "+f"(c[1]), "+f"(c[2]), "+f"(c[3])
        : "r"(a[0]), "r"(a[1]), "r"(a[2]), "r"(a[3]), "r"(b0), "r"(b1));
}
__device__ __forceinline__ void mma16(float* c, const unsigned* a, unsigned b0, unsigned b1) {
    asm volatile(
        "mma.sync.aligned.m16n8k16.row.col.f32.f16.f16.f32 "
        "{%0,%1,%2,%3}, {%4,%5,%6,%7}, {%8,%9}, {%0,%1,%2,%3};"
        : "+f"(c[0]), "+f"(c[1]), "+f"(c[2]), "+f"(c[3])
        : "r"(a[0]), "r"(a[1]), "r"(a[2]), "r"(a[3]), "r"(b0), "r"(b1));
}
__device__ __forceinline__ void ldsm4(unsigned r[4], unsigned addr) {
    asm volatile("ldmatrix.sync.aligned.m8n8.x4.shared.b16 {%0,%1,%2,%3}, [%4];"
                 : "=r"(r[0]), "=r"(r[1]), "=r"(r[2]), "=r"(r[3]) : "r"(addr) : "memory");
}
__device__ __forceinline__ unsigned s2u(const void* p) {
    return (unsigned)__cvta_generic_to_shared(p);
}
__device__ __forceinline__ void cpa16(unsigned dst, const void* src) {
    asm volatile("cp.async.cg.shared.global [%0], [%1], 16;" :: "r"(dst), "l"(src));
}
#define CP_COMMIT() asm volatile("cp.async.commit_group;")
#define CP_WAIT0()  asm volatile("cp.async.wait_group 0;")

// XOR swizzle for [*, 64] f32 tiles (float index)
__device__ __forceinline__ int off(int r, int c) { return r * 64 + (c ^ ((r & 7) << 2)); }
// XOR swizzle for [*, 64] f16 tiles (half index); 16B groups of 8 halves
__device__ __forceinline__ int offh(int r, int grp) { return r * 64 + ((grp ^ (r & 7)) << 3); }

// tf32 A-fragment (16x8) LDSM address
__device__ __forceinline__ unsigned afrag_addr(unsigned base, int lane, int row16, int col8) {
    const int m = lane >> 3, r = lane & 7;
    const int row = row16 + r + ((m & 1) << 3);
    const int col = col8 + ((m >> 1) << 2);
    return base + 4u * ((row << 6) + (col ^ (r << 2)));
}
// tf32 B-fragment pair
__device__ __forceinline__ unsigned bfrag_addr(unsigned base, int lane, int ntp, int ks) {
    const int m = lane >> 3, r = lane & 7;
    const int row = (ntp << 4) + ((m >> 1) << 3) + r;
    const int col = (ks << 3) + ((m & 1) << 2);
    return base + 4u * ((row << 6) + (col ^ (r << 2)));
}
// fp16 A-fragment (16x16) LDSM address (offh swizzle; k16 = 0,16,32,48)
__device__ __forceinline__ unsigned afrag16_addr(unsigned base, int lane, int row16, int k16) {
    const int m = lane >> 3, r = lane & 7;
    const int row = row16 + r + ((m & 1) << 3);
    const int grp = (k16 >> 3) + (m >> 1);
    return base + 2u * (unsigned)offh(row, grp);
}
// fp16 B-fragment pair (n-blocks ntp*16, ntp*16+8 at k16-chunk ks)
__device__ __forceinline__ unsigned bfrag16_addr(unsigned base, int lane, int ntp, int ks) {
    const int m = lane >> 3, r = lane & 7;
    const int row = (ntp << 4) + ((m >> 1) << 3) + r;
    const int grp = (ks << 1) + (m & 1);
    return base + 2u * (unsigned)offh(row, grp);
}

// cp.async of f32 64x64 tile (strided gmem -> off-swizzled smem)
__device__ __forceinline__ void cp_tile64s(unsigned sbase, const float* g, int ldg, int tid) {
    #pragma unroll
    for (int it = 0; it < 4; it++) {
        int i = tid + it * 256, r = i >> 4, c4 = (i & 15) << 2;
        cpa16(sbase + 4u * off(r, c4), g + (size_t)r * ldg + c4);
    }
}
// cp.async of f16 tiles (rows x 64 halves), offh-swizzled
__device__ __forceinline__ void cp_htile128(unsigned sbase, const __half* g, int ldg, int tid) {
    #pragma unroll
    for (int it = 0; it < 4; it++) {
        int i = tid + it * 256, r = i >> 3, gq = i & 7;   // 128 rows x 8 groups
        cpa16(sbase + 2u * (unsigned)offh(r, gq), g + (size_t)r * ldg + gq * 8);
    }
}
__device__ __forceinline__ void cp_htile64(unsigned sbase, const __half* g, int ldg, int tid) {
    #pragma unroll
    for (int it = 0; it < 2; it++) {
        int i = tid + it * 256, r = i >> 3, gq = i & 7;   // 64 rows x 8 groups
        cpa16(sbase + 2u * (unsigned)offh(r, gq), g + (size_t)r * ldg + gq * 8);
    }
}

// ---------------------------------------------------------------------------
// One-shot tf32 pre-rounding of X and the three weight matrices.
// ---------------------------------------------------------------------------
__global__ void __launch_bounds__(256) round_kernel(
    const float4* __restrict__ X,  const float4* __restrict__ Wq,
    const float4* __restrict__ Wk, const float4* __restrict__ Wv)
{
    const int i = blockIdx.x * 256 + threadIdx.x;
    const float4* src; float4* dst; int j;
    if (i < 1048576)      { src = X;  dst = (float4*)g_X;  j = i; }
    else if (i < 1310720) { src = Wq; dst = (float4*)g_Wq; j = i - 1048576; }
    else if (i < 1572864) { src = Wk; dst = (float4*)g_Wk; j = i - 1310720; }
    else                  { src = Wv; dst = (float4*)g_Wv; j = i - 1572864; }
    float4 v = src[j];
    v.x = __uint_as_float(tf32r(v.x)); v.y = __uint_as_float(tf32r(v.y));
    v.z = __uint_as_float(tf32r(v.z)); v.w = __uint_as_float(tf32r(v.w));
    dst[j] = v;
}

// ---------------------------------------------------------------------------
// Projection: Y = X @ W^T. bz<2 -> tf32-rounded g_Q/g_K; bz==2 -> fp16 g_Vt^T.
// ---------------------------------------------------------------------------
__global__ void __launch_bounds__(256, 2) proj_kernel(int unused)
{
    extern __shared__ float dyn[];
    const unsigned uA[2] = { s2u(dyn),         s2u(dyn + 8192)  };
    const unsigned uB[2] = { s2u(dyn + 16384), s2u(dyn + 20480) };

    const int bz = blockIdx.z;
    const float* __restrict__ W = (bz == 0) ? g_Wq : (bz == 1) ? g_Wk : g_Wv;

    const int rowBase = blockIdx.y * 128;
    const int colBase = blockIdx.x * 64;
    const int tid  = threadIdx.x;
    const int warp = tid >> 5;
    const int lane = tid & 31;

    auto issue = [&](int ki, int bi) {
        const int k0 = ki * 64;
        #pragma unroll
        for (int it = 0; it < 8; it++) {
            int i = tid + it * 256, r = i >> 4, c4 = (i & 15) << 2;
            cpa16(uA[bi] + 4u * off(r, c4), g_X + (size_t)(rowBase + r) * DMODEL + k0 + c4);
        }
        #pragma unroll
        for (int it = 0; it < 4; it++) {
            int i = tid + it * 256, r = i >> 4, c4 = (i & 15) << 2;
            cpa16(uB[bi] + 4u * off(r, c4), W + (size_t)(colBase + r) * DMODEL + k0 + c4);
        }
        CP_COMMIT();
    };

    float c[8][4] = {};
    issue(0, 0);
    for (int ki = 0; ki < 16; ki++) {
        CP_WAIT0();
        __syncthreads();
        if (ki + 1 < 16) issue(ki + 1, (ki + 1) & 1);
        const unsigned ua = uA[ki & 1], ub = uB[ki & 1];
        #pragma unroll
        for (int ks = 0; ks < 8; ks++) {
            unsigned aa[4];
            ldsm4(aa, afrag_addr(ua, lane, warp * 16, ks * 8));
            #pragma unroll
            for (int ntp = 0; ntp < 4; ntp++) {
                unsigned bb[4];
                ldsm4(bb, bfrag_addr(ub, lane, ntp, ks));
                mma8(c[2 * ntp],     aa, bb[0], bb[1]);
                mma8(c[2 * ntp + 1], aa, bb[2], bb[3]);
            }
        }
        __syncthreads();
    }

    const int g = lane >> 2, t = lane & 3;
    const int r0 = rowBase + warp * 16 + g;

    if (bz < 2) {
        float* __restrict__ Y = (bz == 0) ? g_Q : g_K;
        #pragma unroll
        for (int nt = 0; nt < 8; nt++) {
            const int col = colBase + nt * 8 + 2 * t;
            float2 lo = make_float2(__uint_as_float(tf32r(c[nt][0])),
                                    __uint_as_float(tf32r(c[nt][1])));
            float2 hi = make_float2(__uint_as_float(tf32r(c[nt][2])),
                                    __uint_as_float(tf32r(c[nt][3])));
            *(float2*)(Y + (size_t)r0 * DMODEL + col)       = lo;
            *(float2*)(Y + (size_t)(r0 + 8) * DMODEL + col) = hi;
        }
    } else {
        // V: scatter fp16 into g_Vt[b,h][dh][s']
        const int b_ = r0 >> 11;
        const int h_ = (r0 >> 7) & 15;
        const int s0 = (r0 & 127) * 16 + (colBase >> 6);
        __half* __restrict__ Vt = g_Vt + (size_t)(b_ * NHEAD + h_) * DHEAD * SEQ;
        #pragma unroll
        for (int nt = 0; nt < 8; nt++) {
            const int d = nt * 8 + 2 * t;
            Vt[(size_t)d * SEQ + s0]             = __float2half_rn(c[nt][0]);
            Vt[(size_t)(d + 1) * SEQ + s0]       = __float2half_rn(c[nt][1]);
            Vt[(size_t)d * SEQ + s0 + 128]       = __float2half_rn(c[nt][2]);
            Vt[(size_t)(d + 1) * SEQ + s0 + 128] = __float2half_rn(c[nt][3]);
        }
    }
}

// ---------------------------------------------------------------------------
// Attention per (b,h). 128-query tile, 256 threads (8 warps x 16 rows).
// Phase 1: tf32 QK^T (Q-frags in regs), write raw exp as fp16 to g_E, den.
// Phase 2: cp.async fp16 E/V tiles; PV via m16n8k16 fp16 mma on raw exp;
//          cooperative fp16->fp32 normalize-write of sim; O scaled once.
// dynamic smem: phase1 2x16KB K tiles; phase2 2x16KB E + 2x8KB V = 48KB.
// ---------------------------------------------------------------------------
__global__ void __launch_bounds__(256, 2) attn_kernel(
    float* __restrict__ out_attn,   // [B, S, D]
    float* __restrict__ out_sim)    // [B, H, S, S]
{
    extern __shared__ float dyn[];
    __shared__ float sInv[128];

    const int qt = blockIdx.x;      // 0..15
    const int h  = blockIdx.y;
    const int b  = blockIdx.z;

    const size_t headOff = ((size_t)b * SEQ + (size_t)h * 128) * DMODEL;
    const float*  __restrict__ Qh  = g_Q + headOff;
    const float*  __restrict__ Kh  = g_K + headOff;
    const __half* __restrict__ VtH = g_Vt + (size_t)(b * NHEAD + h) * DHEAD * SEQ;
    __half* __restrict__ gEh = g_E + (size_t)(b * NHEAD + h) * SEQ * SEQ;
    float*  __restrict__ simB = out_sim + (size_t)(b * NHEAD + h) * SEQ * SEQ;

    const int tid  = threadIdx.x;
    const int warp = tid >> 5;
    const int lane = tid & 31;
    const int g = lane >> 2, t = lane & 3;

    // ---- Q fragments: stage once, keep in registers -------------------------
    {
        float* sQ = dyn;
        #pragma unroll
        for (int it = 0; it < 8; it++) {
            int i = tid + it * 256, r = i >> 4, c4 = (i & 15) << 2;
            *(float4*)&sQ[off(r, c4)] =
                *(const float4*)(Qh + (size_t)(qt * 128 + r) * DHEAD + c4);
        }
    }
    __syncthreads();
    unsigned qa[8][4];
    #pragma unroll
    for (int ks = 0; ks < 8; ks++)
        ldsm4(qa[ks], afrag_addr(s2u(dyn), lane, warp * 16, ks * 8));
    __syncthreads();

    const int rloc = warp * 16 + g;
    const int qrow = qt * 128 + rloc;

    float den0 = 0.0f, den1 = 0.0f;

    // ---------------- Phase 1: tf32 QK^T -> fp16 raw exp ----------------
    const unsigned uK[2] = { s2u(dyn), s2u(dyn + 4096) };
    cp_tile64s(uK[0], Kh, 64, tid); CP_COMMIT();
    for (int kt = 0; kt < 32; kt++) {
        CP_WAIT0();
        __syncthreads();
        if (kt + 1 < 32) {
            cp_tile64s(uK[(kt + 1) & 1], Kh + (size_t)(kt + 1) * 4096, 64, tid);
            CP_COMMIT();
        }
        const unsigned uk = uK[kt & 1];

        float c[8][4] = {};
        #pragma unroll
        for (int ks = 0; ks < 8; ks++) {
            #pragma unroll
            for (int ntp = 0; ntp < 4; ntp++) {
                unsigned bb[4];
                ldsm4(bb, bfrag_addr(uk, lane, ntp, ks));
                mma8(c[2 * ntp],     qa[ks], bb[0], bb[1]);
                mma8(c[2 * ntp + 1], qa[ks], bb[2], bb[3]);
            }
        }

        #pragma unroll
        for (int nt = 0; nt < 8; nt++) {
            float e0 = __expf(c[nt][0] * SCALE_INV);
            float e1 = __expf(c[nt][1] * SCALE_INV);
            float e2 = __expf(c[nt][2] * SCALE_INV);
            float e3 = __expf(c[nt][3] * SCALE_INV);
            const int col = kt * 64 + nt * 8 + 2 * t;
            *(__half2*)(gEh + (size_t)qrow * SEQ + col)       = __floats2half2_rn(e0, e1);
            *(__half2*)(gEh + (size_t)(qrow + 8) * SEQ + col) = __floats2half2_rn(e2, e3);
            den0 += e0 + e1;
            den1 += e2 + e3;
        }
    }
    #pragma unroll
    for (int o = 1; o < 4; o <<= 1) {
        den0 += __shfl_xor_sync(0xffffffffu, den0, o, 4);
        den1 += __shfl_xor_sync(0xffffffffu, den1, o, 4);
    }
    const float inv0 = 1.0f / den0;
    const float inv1 = 1.0f / den1;
    if (t == 0) { sInv[rloc] = inv0; sInv[rloc + 8] = inv1; }

    // ---------------- Phase 2: fp16 PV + cooperative normalize ----------------
    float o2[8][4] = {};
    __syncthreads();                 // phase-1 smem reads done; sInv visible

    const unsigned uE[2] = { s2u(dyn),        s2u(dyn + 4096)  };
    const unsigned uV[2] = { s2u(dyn + 8192), s2u(dyn + 10240) };
    const __half* ebuf[2] = { (const __half*)dyn, (const __half*)(dyn + 4096) };

    cp_htile128(uE[0], gEh + (size_t)(qt * 128) * SEQ, SEQ, tid);
    cp_htile64 (uV[0], VtH, SEQ, tid);
    CP_COMMIT();

    for (int kt = 0; kt < 32; kt++) {
        CP_WAIT0();
        __syncthreads();
        if (kt + 1 < 32) {
            cp_htile128(uE[(kt + 1) & 1], gEh + (size_t)(qt * 128) * SEQ + (kt + 1) * 64, SEQ, tid);
            cp_htile64 (uV[(kt + 1) & 1], VtH + (kt + 1) * 64, SEQ, tid);
            CP_COMMIT();
        }
        const unsigned ue = uE[kt & 1], uv = uV[kt & 1];

        // PV: fp16 m16n8k16, 4 k-chunks x 8 n-blocks
        #pragma unroll
        for (int ks = 0; ks < 4; ks++) {
            unsigned aa[4];
            ldsm4(aa, afrag16_addr(ue, lane, warp * 16, ks * 16));
            #pragma unroll
            for (int ntp = 0; ntp < 4; ntp++) {
                unsigned bb[4];
                ldsm4(bb, bfrag16_addr(uv, lane, ntp, ks));
                mma16(o2[2 * ntp],     aa, bb[0], bb[1]);
                mma16(o2[2 * ntp + 1], aa, bb[2], bb[3]);
            }
        }

        // Cooperative normalize: smem fp16 exp -> fp32 simB (float4, coalesced)
        const __half* eb = ebuf[kt & 1];
        #pragma unroll
        for (int it = 0; it < 8; it++) {
            int i = tid + it * 256, r = i >> 4, c4 = (i & 15) << 2;
            const int idx = offh(r, c4 >> 3) + (c4 & 7);
            const __half2* hp = (const __half2*)(eb + idx);
            float2 f0 = __half22float2(hp[0]);
            float2 f1 = __half22float2(hp[1]);
            const float s = sInv[r];
            float4 v = make_float4(f0.x * s, f0.y * s, f1.x * s, f1.y * s);
            *(float4*)(simB + (size_t)(qt * 128 + r) * SEQ + kt * 64 + c4) = v;
        }
    }

    // Write self_attn with the (0,2,1,3) head transpose; scale by inv here.
    #pragma unroll
    for (int nt = 0; nt < 8; nt++) {
        const int dh = h * DHEAD + nt * 8 + 2 * t;
        *(float2*)(out_attn + ((size_t)b * SEQ + qrow) * DMODEL + dh)
            = make_float2(o2[nt][0] * inv0, o2[nt][1] * inv0);
        *(float2*)(out_attn + ((size_t)b * SEQ + qrow + 8) * DMODEL + dh)
            = make_float2(o2[nt][2] * inv1, o2[nt][3] * inv1);
    }
}

// ---------------------------------------------------------------------------
extern "C" void kernel_launch(void* const* d_in, const int* in_sizes, int n_in,
                              void* d_out, int out_size)
{
    const float* seq = (const float*)d_in[0];
    const float* Wq  = (const float*)d_in[1];
    const float* Wk  = (const float*)d_in[2];
    const float* Wv  = (const float*)d_in[3];

    float* out_attn = (float*)d_out;
    float* out_sim  = (float*)d_out + (size_t)BATCH * SEQ * DMODEL;

    static int attr_set = 0;
    if (!attr_set) {
        cudaFuncSetAttribute(proj_kernel, cudaFuncAttributeMaxDynamicSharedMemorySize, 96 * 1024);
        cudaFuncSetAttribute(attn_kernel, cudaFuncAttributeMaxDynamicSharedMemorySize, 64 * 1024);
        attr_set = 1;
    }

    round_kernel<<<7168, 256>>>((const float4*)seq, (const float4*)Wq,
                                (const float4*)Wk,  (const float4*)Wv);
    proj_kernel<<<dim3(DMODEL / 64, (BATCH * SEQ) / 128, 3), 256, 96 * 1024>>>(0);
    attn_kernel<<<dim3(SEQ / 128, NHEAD, BATCH), 256, 48 * 1024>>>(out_attn, out_sim);
}

// round 9
// speedup vs baseline: 2.2907x; 1.2664x over previous
#include <cuda_runtime.h>
#include <cuda_fp16.h>

#define BATCH 2
#define SEQ   2048
#define DMODEL 1024
#define NHEAD 16
#define DHEAD 64
#define SCALE_INV 0.03125f   // 1/sqrt(1024)

// Scratch (allocation-free rule: __device__ globals). ALL fp16 now.
__device__ __half g_X [BATCH * SEQ * DMODEL];
__device__ __half g_Wq[DMODEL * DMODEL];
__device__ __half g_Wk[DMODEL * DMODEL];
__device__ __half g_Wv[DMODEL * DMODEL];
__device__ __half g_Q [BATCH * SEQ * DMODEL];   // head-contiguous [2048,64] per (b,h)
__device__ __half g_K [BATCH * SEQ * DMODEL];
__device__ __half g_Vt[BATCH * SEQ * DMODEL];   // V^T per head [b,h][dh][s']
__device__ __half g_E [(size_t)BATCH * NHEAD * SEQ * SEQ];  // raw exp (256MB)

// ---- helpers ---------------------------------------------------------------
__device__ __forceinline__ void mma16(float* c, const unsigned* a, unsigned b0, unsigned b1) {
    asm volatile(
        "mma.sync.aligned.m16n8k16.row.col.f32.f16.f16.f32 "
        "{%0,%1,%2,%3}, {%4,%5,%6,%7}, {%8,%9}, {%0,%1,%2,%3};"
        : "+f"(c[0]), "+f"(c[1]), "+f"(c[2]), "+f"(c[3])
        : "r"(a[0]), "r"(a[1]), "r"(a[2]), "r"(a[3]), "r"(b0), "r"(b1));
}
__device__ __forceinline__ void ldsm4(unsigned r[4], unsigned addr) {
    asm volatile("ldmatrix.sync.aligned.m8n8.x4.shared.b16 {%0,%1,%2,%3}, [%4];"
                 : "=r"(r[0]), "=r"(r[1]), "=r"(r[2]), "=r"(r[3]) : "r"(addr) : "memory");
}
__device__ __forceinline__ unsigned s2u(const void* p) {
    return (unsigned)__cvta_generic_to_shared(p);
}
__device__ __forceinline__ void cpa16(unsigned dst, const void* src) {
    asm volatile("cp.async.cg.shared.global [%0], [%1], 16;" :: "r"(dst), "l"(src));
}
#define CP_COMMIT() asm volatile("cp.async.commit_group;")
#define CP_WAIT0()  asm volatile("cp.async.wait_group 0;")
#define CP_WAIT1()  asm volatile("cp.async.wait_group 1;")
#define CP_WAIT2()  asm volatile("cp.async.wait_group 2;")

// XOR swizzle for [*, 64] f16 tiles (half index); 16B groups of 8 halves
__device__ __forceinline__ int offh(int r, int grp) { return r * 64 + ((grp ^ (r & 7)) << 3); }

// fp16 A-fragment (16x16) LDSM address (k16 = 0,16,32,48)
__device__ __forceinline__ unsigned afrag16_addr(unsigned base, int lane, int row16, int k16) {
    const int m = lane >> 3, r = lane & 7;
    const int row = row16 + r + ((m & 1) << 3);
    const int grp = (k16 >> 3) + (m >> 1);
    return base + 2u * (unsigned)offh(row, grp);
}
// fp16 B-fragment pair (n-blocks ntp*16, ntp*16+8 at k16-chunk ks)
__device__ __forceinline__ unsigned bfrag16_addr(unsigned base, int lane, int ntp, int ks) {
    const int m = lane >> 3, r = lane & 7;
    const int row = (ntp << 4) + ((m >> 1) << 3) + r;
    const int grp = (ks << 1) + (m & 1);
    return base + 2u * (unsigned)offh(row, grp);
}

// cp.async of f16 tiles (rows x 64 halves), offh-swizzled, strided gmem
__device__ __forceinline__ void cp_htile128(unsigned sbase, const __half* g, int ldg, int tid) {
    #pragma unroll
    for (int it = 0; it < 4; it++) {
        int i = tid + it * 256, r = i >> 3, gq = i & 7;
        cpa16(sbase + 2u * (unsigned)offh(r, gq), g + (size_t)r * ldg + gq * 8);
    }
}
__device__ __forceinline__ void cp_htile64(unsigned sbase, const __half* g, int ldg, int tid) {
    #pragma unroll
    for (int it = 0; it < 2; it++) {
        int i = tid + it * 256, r = i >> 3, gq = i & 7;
        cpa16(sbase + 2u * (unsigned)offh(r, gq), g + (size_t)r * ldg + gq * 8);
    }
}

// ---------------------------------------------------------------------------
// One-shot fp16 conversion of X and the three weight matrices.
// ---------------------------------------------------------------------------
__global__ void __launch_bounds__(256) cvt_kernel(
    const float4* __restrict__ X,  const float4* __restrict__ Wq,
    const float4* __restrict__ Wk, const float4* __restrict__ Wv)
{
    const int i = blockIdx.x * 256 + threadIdx.x;
    const float4* src; __half* dst; int j;
    if (i < 1048576)      { src = X;  dst = g_X;  j = i; }
    else if (i < 1310720) { src = Wq; dst = g_Wq; j = i - 1048576; }
    else if (i < 1572864) { src = Wk; dst = g_Wk; j = i - 1310720; }
    else                  { src = Wv; dst = g_Wv; j = i - 1572864; }
    float4 v = src[j];
    __half2 lo = __floats2half2_rn(v.x, v.y);
    __half2 hi = __floats2half2_rn(v.z, v.w);
    *(__half2*)(dst + 4 * (size_t)j)     = lo;
    *(__half2*)(dst + 4 * (size_t)j + 2) = hi;
}

// ---------------------------------------------------------------------------
// Projection: Y = X @ W^T, fp16 mma, cp.async double-buffered.
// 128x64 tiles, 256 threads. bz<2 -> fp16 g_Q/g_K; bz==2 -> fp16 g_Vt^T.
// smem: A 2x16KB + B 2x8KB = 48KB dynamic.
// ---------------------------------------------------------------------------
__global__ void __launch_bounds__(256, 2) proj_kernel(int unused)
{
    extern __shared__ char dynC[];
    const unsigned uA[2] = { s2u(dynC),         s2u(dynC + 16384) };
    const unsigned uB[2] = { s2u(dynC + 32768), s2u(dynC + 40960) };

    const int bz = blockIdx.z;
    const __half* __restrict__ W = (bz == 0) ? g_Wq : (bz == 1) ? g_Wk : g_Wv;

    const int rowBase = blockIdx.y * 128;
    const int colBase = blockIdx.x * 64;
    const int tid  = threadIdx.x;
    const int warp = tid >> 5;
    const int lane = tid & 31;

    auto issue = [&](int ki, int bi) {
        const int k0 = ki * 64;
        cp_htile128(uA[bi], g_X + (size_t)rowBase * DMODEL + k0, DMODEL, tid);
        cp_htile64 (uB[bi], W   + (size_t)colBase * DMODEL + k0, DMODEL, tid);
        CP_COMMIT();
    };

    float c[8][4] = {};
    issue(0, 0);
    for (int ki = 0; ki < 16; ki++) {
        CP_WAIT0();
        __syncthreads();
        if (ki + 1 < 16) issue(ki + 1, (ki + 1) & 1);
        const unsigned ua = uA[ki & 1], ub = uB[ki & 1];
        #pragma unroll
        for (int kc = 0; kc < 4; kc++) {
            unsigned aa[4];
            ldsm4(aa, afrag16_addr(ua, lane, warp * 16, kc * 16));
            #pragma unroll
            for (int ntp = 0; ntp < 4; ntp++) {
                unsigned bb[4];
                ldsm4(bb, bfrag16_addr(ub, lane, ntp, kc));
                mma16(c[2 * ntp],     aa, bb[0], bb[1]);
                mma16(c[2 * ntp + 1], aa, bb[2], bb[3]);
            }
        }
    }

    const int g = lane >> 2, t = lane & 3;
    const int r0 = rowBase + warp * 16 + g;

    if (bz < 2) {
        __half* __restrict__ Y = (bz == 0) ? g_Q : g_K;
        #pragma unroll
        for (int nt = 0; nt < 8; nt++) {
            const int col = colBase + nt * 8 + 2 * t;
            *(__half2*)(Y + (size_t)r0 * DMODEL + col)       = __floats2half2_rn(c[nt][0], c[nt][1]);
            *(__half2*)(Y + (size_t)(r0 + 8) * DMODEL + col) = __floats2half2_rn(c[nt][2], c[nt][3]);
        }
    } else {
        // V: scatter fp16 into g_Vt[b,h][dh][s']
        const int b_ = r0 >> 11;
        const int h_ = (r0 >> 7) & 15;
        const int s0 = (r0 & 127) * 16 + (colBase >> 6);
        __half* __restrict__ Vt = g_Vt + (size_t)(b_ * NHEAD + h_) * DHEAD * SEQ;
        #pragma unroll
        for (int nt = 0; nt < 8; nt++) {
            const int d = nt * 8 + 2 * t;
            Vt[(size_t)d * SEQ + s0]             = __float2half_rn(c[nt][0]);
            Vt[(size_t)(d + 1) * SEQ + s0]       = __float2half_rn(c[nt][1]);
            Vt[(size_t)d * SEQ + s0 + 128]       = __float2half_rn(c[nt][2]);
            Vt[(size_t)(d + 1) * SEQ + s0 + 128] = __float2half_rn(c[nt][3]);
        }
    }
}

// ---------------------------------------------------------------------------
// Attention per (b,h). 128-query tile, 256 threads (8 warps x 16 rows).
// Phase 1: fp16 QK^T (Q-frags in regs), fp16 raw exp -> g_E, den accum.
//          3-stage cp.async ring on K tiles.
// Phase 2: 3-stage ring on (E,V) tile pairs; fp16 PV mma on raw exp;
//          cooperative normalize-write of sim; O scaled once at the end.
// dynamic smem: 72KB (phase1: sQ 16K + 3x8K K ring; phase2: 3x16K E + 3x8K V).
// ---------------------------------------------------------------------------
__global__ void __launch_bounds__(256, 2) attn_kernel(
    float* __restrict__ out_attn,   // [B, S, D]
    float* __restrict__ out_sim)    // [B, H, S, S]
{
    extern __shared__ char dynC[];
    __shared__ float sInv[128];

    const int qt = blockIdx.x;      // 0..15
    const int h  = blockIdx.y;
    const int b  = blockIdx.z;

    const size_t headOff = ((size_t)b * SEQ + (size_t)h * 128) * DMODEL;
    const __half* __restrict__ Qh  = g_Q + headOff;
    const __half* __restrict__ Kh  = g_K + headOff;
    const __half* __restrict__ VtH = g_Vt + (size_t)(b * NHEAD + h) * DHEAD * SEQ;
    __half* __restrict__ gEh  = g_E + (size_t)(b * NHEAD + h) * SEQ * SEQ;
    float*  __restrict__ simB = out_sim + (size_t)(b * NHEAD + h) * SEQ * SEQ;

    const int tid  = threadIdx.x;
    const int warp = tid >> 5;
    const int lane = tid & 31;
    const int g = lane >> 2, t = lane & 3;

    const int rloc = warp * 16 + g;
    const int qrow = qt * 128 + rloc;

    // ---------------- Phase 1: fp16 QK^T -> fp16 raw exp ----------------
    const unsigned uQ = s2u(dynC);
    const unsigned uKr[3] = { s2u(dynC + 16384), s2u(dynC + 24576), s2u(dynC + 32768) };

    cp_htile128(uQ, Qh + (size_t)qt * 128 * DHEAD, DHEAD, tid); CP_COMMIT();
    cp_htile64(uKr[0], Kh,        DHEAD, tid); CP_COMMIT();
    cp_htile64(uKr[1], Kh + 4096, DHEAD, tid); CP_COMMIT();
    CP_WAIT2();                    // Q tile resident (K0/K1 may be in flight)
    __syncthreads();

    unsigned qa[4][4];
    #pragma unroll
    for (int kc = 0; kc < 4; kc++)
        ldsm4(qa[kc], afrag16_addr(uQ, lane, warp * 16, kc * 16));

    float den0 = 0.0f, den1 = 0.0f;

    for (int kt = 0; kt < 32; kt++) {
        if (kt < 31) { CP_WAIT1(); } else { CP_WAIT0(); }
        __syncthreads();
        if (kt + 2 < 32) {
            cp_htile64(uKr[(kt + 2) % 3], Kh + (size_t)(kt + 2) * 4096, DHEAD, tid);
            CP_COMMIT();
        }
        const unsigned uk = uKr[kt % 3];

        float c[8][4] = {};
        #pragma unroll
        for (int kc = 0; kc < 4; kc++) {
            #pragma unroll
            for (int ntp = 0; ntp < 4; ntp++) {
                unsigned bb[4];
                ldsm4(bb, bfrag16_addr(uk, lane, ntp, kc));
                mma16(c[2 * ntp],     qa[kc], bb[0], bb[1]);
                mma16(c[2 * ntp + 1], qa[kc], bb[2], bb[3]);
            }
        }

        #pragma unroll
        for (int nt = 0; nt < 8; nt++) {
            float e0 = __expf(c[nt][0] * SCALE_INV);
            float e1 = __expf(c[nt][1] * SCALE_INV);
            float e2 = __expf(c[nt][2] * SCALE_INV);
            float e3 = __expf(c[nt][3] * SCALE_INV);
            const int col = kt * 64 + nt * 8 + 2 * t;
            *(__half2*)(gEh + (size_t)qrow * SEQ + col)       = __floats2half2_rn(e0, e1);
            *(__half2*)(gEh + (size_t)(qrow + 8) * SEQ + col) = __floats2half2_rn(e2, e3);
            den0 += e0 + e1;
            den1 += e2 + e3;
        }
    }
    #pragma unroll
    for (int o = 1; o < 4; o <<= 1) {
        den0 += __shfl_xor_sync(0xffffffffu, den0, o, 4);
        den1 += __shfl_xor_sync(0xffffffffu, den1, o, 4);
    }
    const float inv0 = 1.0f / den0;
    const float inv1 = 1.0f / den1;
    if (t == 0) { sInv[rloc] = inv0; sInv[rloc + 8] = inv1; }

    // ---------------- Phase 2: fp16 PV + cooperative normalize ----------------
    float o2[8][4] = {};
    __syncthreads();                 // phase-1 smem reads done; sInv visible

    const unsigned uEr[3] = { s2u(dynC),         s2u(dynC + 16384), s2u(dynC + 32768) };
    const unsigned uVr[3] = { s2u(dynC + 49152), s2u(dynC + 57344), s2u(dynC + 65536) };

    auto issue_ev = [&](int kt, int slot) {
        cp_htile128(uEr[slot], gEh + (size_t)(qt * 128) * SEQ + kt * 64, SEQ, tid);
        cp_htile64 (uVr[slot], VtH + kt * 64, SEQ, tid);
        CP_COMMIT();
    };
    issue_ev(0, 0);
    issue_ev(1, 1);

    for (int kt = 0; kt < 32; kt++) {
        if (kt < 31) { CP_WAIT1(); } else { CP_WAIT0(); }
        __syncthreads();
        if (kt + 2 < 32) issue_ev(kt + 2, (kt + 2) % 3);

        const unsigned ue = uEr[kt % 3], uv = uVr[kt % 3];

        #pragma unroll
        for (int kc = 0; kc < 4; kc++) {
            unsigned aa[4];
            ldsm4(aa, afrag16_addr(ue, lane, warp * 16, kc * 16));
            #pragma unroll
            for (int ntp = 0; ntp < 4; ntp++) {
                unsigned bb[4];
                ldsm4(bb, bfrag16_addr(uv, lane, ntp, kc));
                mma16(o2[2 * ntp],     aa, bb[0], bb[1]);
                mma16(o2[2 * ntp + 1], aa, bb[2], bb[3]);
            }
        }

        // Cooperative normalize: smem fp16 exp -> fp32 simB (float4, coalesced)
        const __half* eb = (const __half*)(dynC + (kt % 3) * 16384);
        #pragma unroll
        for (int it = 0; it < 8; it++) {
            int i = tid + it * 256, r = i >> 4, c4 = (i & 15) << 2;
            const int idx = offh(r, c4 >> 3) + (c4 & 7);
            const __half2* hp = (const __half2*)(eb + idx);
            float2 f0 = __half22float2(hp[0]);
            float2 f1 = __half22float2(hp[1]);
            const float s = sInv[r];
            float4 v = make_float4(f0.x * s, f0.y * s, f1.x * s, f1.y * s);
            *(float4*)(simB + (size_t)(qt * 128 + r) * SEQ + kt * 64 + c4) = v;
        }
    }

    // Write self_attn with the (0,2,1,3) head transpose; scale by inv here.
    #pragma unroll
    for (int nt = 0; nt < 8; nt++) {
        const int dh = h * DHEAD + nt * 8 + 2 * t;
        *(float2*)(out_attn + ((size_t)b * SEQ + qrow) * DMODEL + dh)
            = make_float2(o2[nt][0] * inv0, o2[nt][1] * inv0);
        *(float2*)(out_attn + ((size_t)b * SEQ + qrow + 8) * DMODEL + dh)
            = make_float2(o2[nt][2] * inv1, o2[nt][3] * inv1);
    }
}

// ---------------------------------------------------------------------------
extern "C" void kernel_launch(void* const* d_in, const int* in_sizes, int n_in,
                              void* d_out, int out_size)
{
    const float* seq = (const float*)d_in[0];
    const float* Wq  = (const float*)d_in[1];
    const float* Wk  = (const float*)d_in[2];
    const float* Wv  = (const float*)d_in[3];

    float* out_attn = (float*)d_out;
    float* out_sim  = (float*)d_out + (size_t)BATCH * SEQ * DMODEL;

    static int attr_set = 0;
    if (!attr_set) {
        cudaFuncSetAttribute(proj_kernel, cudaFuncAttributeMaxDynamicSharedMemorySize, 64 * 1024);
        cudaFuncSetAttribute(attn_kernel, cudaFuncAttributeMaxDynamicSharedMemorySize, 96 * 1024);
        attr_set = 1;
    }

    cvt_kernel<<<7168, 256>>>((const float4*)seq, (const float4*)Wq,
                              (const float4*)Wk,  (const float4*)Wv);
    proj_kernel<<<dim3(DMODEL / 64, (BATCH * SEQ) / 128, 3), 256, 48 * 1024>>>(0);
    attn_kernel<<<dim3(SEQ / 128, NHEAD, BATCH), 256, 72 * 1024>>>(out_attn, out_sim);
}

// round 15
// speedup vs baseline: 2.4524x; 1.0706x over previous
#include <cuda_runtime.h>
#include <cuda_fp16.h>

#define BATCH 2
#define SEQ   2048
#define DMODEL 1024
#define NHEAD 16
#define DHEAD 64
#define SCALE_INV 0.03125f   // 1/sqrt(1024)

// Scratch (allocation-free rule: __device__ globals). All fp16.
__device__ __half g_X [BATCH * SEQ * DMODEL];
__device__ __half g_Wq[DMODEL * DMODEL];
__device__ __half g_Wk[DMODEL * DMODEL];
__device__ __half g_Wv[DMODEL * DMODEL];
__device__ __half g_Q [BATCH * SEQ * DMODEL];   // head-contiguous [2048,64] per (b,h)
__device__ __half g_K [BATCH * SEQ * DMODEL];
__device__ __half g_Vt[BATCH * SEQ * DMODEL];   // V^T per head [b,h][dh][s']

// ---- helpers ---------------------------------------------------------------
__device__ __forceinline__ void mma16(float* c, const unsigned* a, unsigned b0, unsigned b1) {
    asm volatile(
        "mma.sync.aligned.m16n8k16.row.col.f32.f16.f16.f32 "
        "{%0,%1,%2,%3}, {%4,%5,%6,%7}, {%8,%9}, {%0,%1,%2,%3};"
        : "+f"(c[0]), "+f"(c[1]), "+f"(c[2]), "+f"(c[3])
        : "r"(a[0]), "r"(a[1]), "r"(a[2]), "r"(a[3]), "r"(b0), "r"(b1));
}
__device__ __forceinline__ void ldsm4(unsigned r[4], unsigned addr) {
    asm volatile("ldmatrix.sync.aligned.m8n8.x4.shared.b16 {%0,%1,%2,%3}, [%4];"
                 : "=r"(r[0]), "=r"(r[1]), "=r"(r[2]), "=r"(r[3]) : "r"(addr) : "memory");
}
// pack two fp32 -> one f16x2 register (lo = first arg, hi = second arg)
__device__ __forceinline__ unsigned packh2(float lo, float hi) {
    unsigned r;
    asm("cvt.rn.f16x2.f32 %0, %1, %2;" : "=r"(r) : "f"(hi), "f"(lo));
    return r;
}
__device__ __forceinline__ unsigned s2u(const void* p) {
    return (unsigned)__cvta_generic_to_shared(p);
}
__device__ __forceinline__ void cpa16(unsigned dst, const void* src) {
    asm volatile("cp.async.cg.shared.global [%0], [%1], 16;" :: "r"(dst), "l"(src));
}
#define CP_COMMIT() asm volatile("cp.async.commit_group;")
#define CP_WAIT0()  asm volatile("cp.async.wait_group 0;")
#define CP_WAIT1()  asm volatile("cp.async.wait_group 1;")
#define CP_WAIT2()  asm volatile("cp.async.wait_group 2;")

// XOR swizzle for [*, 64] f16 tiles (half index); 16B groups of 8 halves
__device__ __forceinline__ int offh(int r, int grp) { return r * 64 + ((grp ^ (r & 7)) << 3); }

// fp16 A-fragment (16x16) LDSM address (k16 = 0,16,32,48)
__device__ __forceinline__ unsigned afrag16_addr(unsigned base, int lane, int row16, int k16) {
    const int m = lane >> 3, r = lane & 7;
    const int row = row16 + r + ((m & 1) << 3);
    const int grp = (k16 >> 3) + (m >> 1);
    return base + 2u * (unsigned)offh(row, grp);
}
// fp16 B-fragment pair (n-blocks ntp*16, ntp*16+8 at k16-chunk ks)
__device__ __forceinline__ unsigned bfrag16_addr(unsigned base, int lane, int ntp, int ks) {
    const int m = lane >> 3, r = lane & 7;
    const int row = (ntp << 4) + ((m >> 1) << 3) + r;
    const int grp = (ks << 1) + (m & 1);
    return base + 2u * (unsigned)offh(row, grp);
}

// cp.async of f16 tiles (rows x 64 halves), offh-swizzled, strided gmem
__device__ __forceinline__ void cp_htile128(unsigned sbase, const __half* g, int ldg, int tid) {
    #pragma unroll
    for (int it = 0; it < 4; it++) {
        int i = tid + it * 256, r = i >> 3, gq = i & 7;
        cpa16(sbase + 2u * (unsigned)offh(r, gq), g + (size_t)r * ldg + gq * 8);
    }
}
__device__ __forceinline__ void cp_htile64(unsigned sbase, const __half* g, int ldg, int tid) {
    #pragma unroll
    for (int it = 0; it < 2; it++) {
        int i = tid + it * 256, r = i >> 3, gq = i & 7;
        cpa16(sbase + 2u * (unsigned)offh(r, gq), g + (size_t)r * ldg + gq * 8);
    }
}

// ---------------------------------------------------------------------------
// One-shot fp16 conversion of X and the three weight matrices.
// ---------------------------------------------------------------------------
__global__ void __launch_bounds__(256) cvt_kernel(
    const float4* __restrict__ X,  const float4* __restrict__ Wq,
    const float4* __restrict__ Wk, const float4* __restrict__ Wv)
{
    const int i = blockIdx.x * 256 + threadIdx.x;
    const float4* src; __half* dst; int j;
    if (i < 1048576)      { src = X;  dst = g_X;  j = i; }
    else if (i < 1310720) { src = Wq; dst = g_Wq; j = i - 1048576; }
    else if (i < 1572864) { src = Wk; dst = g_Wk; j = i - 1310720; }
    else                  { src = Wv; dst = g_Wv; j = i - 1572864; }
    float4 v = src[j];
    *(__half2*)(dst + 4 * (size_t)j)     = __floats2half2_rn(v.x, v.y);
    *(__half2*)(dst + 4 * (size_t)j + 2) = __floats2half2_rn(v.z, v.w);
}

// ---------------------------------------------------------------------------
// Projection: Y = X @ W^T, fp16 mma, cp.async double-buffered.
// 128x64 tiles, 256 threads. bz<2 -> fp16 g_Q/g_K; bz==2 -> fp16 g_Vt^T.
// ---------------------------------------------------------------------------
__global__ void __launch_bounds__(256, 2) proj_kernel(int unused)
{
    extern __shared__ char dynC[];
    const unsigned uA[2] = { s2u(dynC),         s2u(dynC + 16384) };
    const unsigned uB[2] = { s2u(dynC + 32768), s2u(dynC + 40960) };

    const int bz = blockIdx.z;
    const __half* __restrict__ W = (bz == 0) ? g_Wq : (bz == 1) ? g_Wk : g_Wv;

    const int rowBase = blockIdx.y * 128;
    const int colBase = blockIdx.x * 64;
    const int tid  = threadIdx.x;
    const int warp = tid >> 5;
    const int lane = tid & 31;

    auto issue = [&](int ki, int bi) {
        const int k0 = ki * 64;
        cp_htile128(uA[bi], g_X + (size_t)rowBase * DMODEL + k0, DMODEL, tid);
        cp_htile64 (uB[bi], W   + (size_t)colBase * DMODEL + k0, DMODEL, tid);
        CP_COMMIT();
    };

    float c[8][4] = {};
    issue(0, 0);
    for (int ki = 0; ki < 16; ki++) {
        CP_WAIT0();
        __syncthreads();
        if (ki + 1 < 16) issue(ki + 1, (ki + 1) & 1);
        const unsigned ua = uA[ki & 1], ub = uB[ki & 1];
        #pragma unroll
        for (int kc = 0; kc < 4; kc++) {
            unsigned aa[4];
            ldsm4(aa, afrag16_addr(ua, lane, warp * 16, kc * 16));
            #pragma unroll
            for (int ntp = 0; ntp < 4; ntp++) {
                unsigned bb[4];
                ldsm4(bb, bfrag16_addr(ub, lane, ntp, kc));
                mma16(c[2 * ntp],     aa, bb[0], bb[1]);
                mma16(c[2 * ntp + 1], aa, bb[2], bb[3]);
            }
        }
    }

    const int g = lane >> 2, t = lane & 3;
    const int r0 = rowBase + warp * 16 + g;

    if (bz < 2) {
        __half* __restrict__ Y = (bz == 0) ? g_Q : g_K;
        #pragma unroll
        for (int nt = 0; nt < 8; nt++) {
            const int col = colBase + nt * 8 + 2 * t;
            *(__half2*)(Y + (size_t)r0 * DMODEL + col)       = __floats2half2_rn(c[nt][0], c[nt][1]);
            *(__half2*)(Y + (size_t)(r0 + 8) * DMODEL + col) = __floats2half2_rn(c[nt][2], c[nt][3]);
        }
    } else {
        // V: scatter fp16 into g_Vt[b,h][dh][s']
        const int b_ = r0 >> 11;
        const int h_ = (r0 >> 7) & 15;
        const int s0 = (r0 & 127) * 16 + (colBase >> 6);
        __half* __restrict__ Vt = g_Vt + (size_t)(b_ * NHEAD + h_) * DHEAD * SEQ;
        #pragma unroll
        for (int nt = 0; nt < 8; nt++) {
            const int d = nt * 8 + 2 * t;
            Vt[(size_t)d * SEQ + s0]             = __float2half_rn(c[nt][0]);
            Vt[(size_t)(d + 1) * SEQ + s0]       = __float2half_rn(c[nt][1]);
            Vt[(size_t)d * SEQ + s0 + 128]       = __float2half_rn(c[nt][2]);
            Vt[(size_t)(d + 1) * SEQ + s0 + 128] = __float2half_rn(c[nt][3]);
        }
    }
}

// ---------------------------------------------------------------------------
// Attention per (b,h). 128-query tile, 256 threads (8 warps x 16 rows).
// Phase 1: fp16 QK^T + exp + den accumulation (NO memory writes).
// Phase 2: recompute QK^T, exp, write NORMALIZED sim fp32 directly, and
//          PV mma with A-fragments packed straight from the exp registers
//          (C-layout == A-layout up to per-thread f16x2 packing; no smem E).
// dynamic smem: sQ 16KB + K ring 3x8KB + V ring 3x8KB = 64KB.
// ---------------------------------------------------------------------------
__global__ void __launch_bounds__(256, 2) attn_kernel(
    float* __restrict__ out_attn,   // [B, S, D]
    float* __restrict__ out_sim)    // [B, H, S, S]
{
    extern __shared__ char dynC[];

    const int qt = blockIdx.x;      // 0..15
    const int h  = blockIdx.y;
    const int b  = blockIdx.z;

    const size_t headOff = ((size_t)b * SEQ + (size_t)h * 128) * DMODEL;
    const __half* __restrict__ Qh  = g_Q + headOff;
    const __half* __restrict__ Kh  = g_K + headOff;
    const __half* __restrict__ VtH = g_Vt + (size_t)(b * NHEAD + h) * DHEAD * SEQ;
    float* __restrict__ simB = out_sim + (size_t)(b * NHEAD + h) * SEQ * SEQ;

    const int tid  = threadIdx.x;
    const int warp = tid >> 5;
    const int lane = tid & 31;
    const int g = lane >> 2, t = lane & 3;

    const int rloc = warp * 16 + g;
    const int qrow = qt * 128 + rloc;

    const unsigned uQ = s2u(dynC);
    const unsigned uKr[3] = { s2u(dynC + 16384), s2u(dynC + 24576), s2u(dynC + 32768) };
    const unsigned uVr[3] = { s2u(dynC + 40960), s2u(dynC + 49152), s2u(dynC + 57344) };

    // ---- Q tile + fragments (kept in registers for both phases) ------------
    cp_htile128(uQ, Qh + (size_t)qt * 128 * DHEAD, DHEAD, tid); CP_COMMIT();
    cp_htile64(uKr[0], Kh,        DHEAD, tid); CP_COMMIT();
    cp_htile64(uKr[1], Kh + 4096, DHEAD, tid); CP_COMMIT();
    CP_WAIT2();                    // Q resident (K0/K1 may still be in flight)
    __syncthreads();

    unsigned qa[4][4];
    #pragma unroll
    for (int kc = 0; kc < 4; kc++)
        ldsm4(qa[kc], afrag16_addr(uQ, lane, warp * 16, kc * 16));

    // ---------------- Phase 1: den only, no writes ----------------
    float den0 = 0.0f, den1 = 0.0f;
    for (int kt = 0; kt < 32; kt++) {
        if (kt < 31) { CP_WAIT1(); } else { CP_WAIT0(); }
        __syncthreads();
        if (kt + 2 < 32) {
            cp_htile64(uKr[(kt + 2) % 3], Kh + (size_t)(kt + 2) * 4096, DHEAD, tid);
            CP_COMMIT();
        }
        const unsigned uk = uKr[kt % 3];

        float c[8][4] = {};
        #pragma unroll
        for (int kc = 0; kc < 4; kc++) {
            #pragma unroll
            for (int ntp = 0; ntp < 4; ntp++) {
                unsigned bb[4];
                ldsm4(bb, bfrag16_addr(uk, lane, ntp, kc));
                mma16(c[2 * ntp],     qa[kc], bb[0], bb[1]);
                mma16(c[2 * ntp + 1], qa[kc], bb[2], bb[3]);
            }
        }
        #pragma unroll
        for (int nt = 0; nt < 8; nt++) {
            den0 += __expf(c[nt][0] * SCALE_INV) + __expf(c[nt][1] * SCALE_INV);
            den1 += __expf(c[nt][2] * SCALE_INV) + __expf(c[nt][3] * SCALE_INV);
        }
    }
    #pragma unroll
    for (int o = 1; o < 4; o <<= 1) {
        den0 += __shfl_xor_sync(0xffffffffu, den0, o, 4);
        den1 += __shfl_xor_sync(0xffffffffu, den1, o, 4);
    }
    const float inv0 = 1.0f / den0;
    const float inv1 = 1.0f / den1;

    // ---------------- Phase 2: recompute + sim write + PV ----------------
    float o2[8][4] = {};
    __syncthreads();                  // phase-1 ring reads done

    auto issue_kv = [&](int kt, int slot) {
        cp_htile64(uKr[slot], Kh  + (size_t)kt * 4096, DHEAD, tid);
        cp_htile64(uVr[slot], VtH + kt * 64,           SEQ,   tid);
        CP_COMMIT();
    };
    issue_kv(0, 0);
    issue_kv(1, 1);

    for (int kt = 0; kt < 32; kt++) {
        if (kt < 31) { CP_WAIT1(); } else { CP_WAIT0(); }
        __syncthreads();
        if (kt + 2 < 32) issue_kv(kt + 2, (kt + 2) % 3);

        const unsigned uk = uKr[kt % 3], uv = uVr[kt % 3];

        // QK^T recompute
        float c[8][4] = {};
        #pragma unroll
        for (int kc = 0; kc < 4; kc++) {
            #pragma unroll
            for (int ntp = 0; ntp < 4; ntp++) {
                unsigned bb[4];
                ldsm4(bb, bfrag16_addr(uk, lane, ntp, kc));
                mma16(c[2 * ntp],     qa[kc], bb[0], bb[1]);
                mma16(c[2 * ntp + 1], qa[kc], bb[2], bb[3]);
            }
        }

        // exp; write normalized sim; keep raw exp in c for PV packing
        #pragma unroll
        for (int nt = 0; nt < 8; nt++) {
            float e0 = __expf(c[nt][0] * SCALE_INV);
            float e1 = __expf(c[nt][1] * SCALE_INV);
            float e2 = __expf(c[nt][2] * SCALE_INV);
            float e3 = __expf(c[nt][3] * SCALE_INV);
            const int col = kt * 64 + nt * 8 + 2 * t;
            *(float2*)(simB + (size_t)qrow * SEQ + col)       = make_float2(e0 * inv0, e1 * inv0);
            *(float2*)(simB + (size_t)(qrow + 8) * SEQ + col) = make_float2(e2 * inv1, e3 * inv1);
            c[nt][0] = e0; c[nt][1] = e1; c[nt][2] = e2; c[nt][3] = e3;
        }

        // PV: A-frags packed directly from exp registers (no smem, no shuffle)
        #pragma unroll
        for (int kc = 0; kc < 4; kc++) {
            unsigned aa[4];
            aa[0] = packh2(c[2 * kc][0],     c[2 * kc][1]);
            aa[1] = packh2(c[2 * kc][2],     c[2 * kc][3]);
            aa[2] = packh2(c[2 * kc + 1][0], c[2 * kc + 1][1]);
            aa[3] = packh2(c[2 * kc + 1][2], c[2 * kc + 1][3]);
            #pragma unroll
            for (int ntp = 0; ntp < 4; ntp++) {
                unsigned bb[4];
                ldsm4(bb, bfrag16_addr(uv, lane, ntp, kc));
                mma16(o2[2 * ntp],     aa, bb[0], bb[1]);
                mma16(o2[2 * ntp + 1], aa, bb[2], bb[3]);
            }
        }
    }

    // Write self_attn with the (0,2,1,3) head transpose; scale by inv here.
    #pragma unroll
    for (int nt = 0; nt < 8; nt++) {
        const int dh = h * DHEAD + nt * 8 + 2 * t;
        *(float2*)(out_attn + ((size_t)b * SEQ + qrow) * DMODEL + dh)
            = make_float2(o2[nt][0] * inv0, o2[nt][1] * inv0);
        *(float2*)(out_attn + ((size_t)b * SEQ + qrow + 8) * DMODEL + dh)
            = make_float2(o2[nt][2] * inv1, o2[nt][3] * inv1);
    }
}

// ---------------------------------------------------------------------------
extern "C" void kernel_launch(void* const* d_in, const int* in_sizes, int n_in,
                              void* d_out, int out_size)
{
    const float* seq = (const float*)d_in[0];
    const float* Wq  = (const float*)d_in[1];
    const float* Wk  = (const float*)d_in[2];
    const float* Wv  = (const float*)d_in[3];

    float* out_attn = (float*)d_out;
    float* out_sim  = (float*)d_out + (size_t)BATCH * SEQ * DMODEL;

    static int attr_set = 0;
    if (!attr_set) {
        cudaFuncSetAttribute(proj_kernel, cudaFuncAttributeMaxDynamicSharedMemorySize, 64 * 1024);
        cudaFuncSetAttribute(attn_kernel, cudaFuncAttributeMaxDynamicSharedMemorySize, 64 * 1024);
        attr_set = 1;
    }

    cvt_kernel<<<7168, 256>>>((const float4*)seq, (const float4*)Wq,
                              (const float4*)Wk,  (const float4*)Wv);
    proj_kernel<<<dim3(DMODEL / 64, (BATCH * SEQ) / 128, 3), 256, 48 * 1024>>>(0);
    attn_kernel<<<dim3(SEQ / 128, NHEAD, BATCH), 256, 64 * 1024>>>(out_attn, out_sim);
}

// round 17
// speedup vs baseline: 2.6377x; 1.0756x over previous
#include <cuda_runtime.h>
#include <cuda_fp16.h>

#define BATCH 2
#define SEQ   2048
#define DMODEL 1024
#define NHEAD 16
#define DHEAD 64
// log2(e)/32 — folded into Q at projection time so exp(q.k/32) == ex2(logit)
#define QSCALE 0.04508422f

// Scratch (allocation-free rule: __device__ globals). All fp16.
__device__ __half g_X [BATCH * SEQ * DMODEL];
__device__ __half g_Wq[DMODEL * DMODEL];
__device__ __half g_Wk[DMODEL * DMODEL];
__device__ __half g_Wv[DMODEL * DMODEL];
__device__ __half g_Q [BATCH * SEQ * DMODEL];   // head-contiguous [2048,64]; PRE-SCALED by QSCALE
__device__ __half g_K [BATCH * SEQ * DMODEL];
__device__ __half g_Vt[BATCH * SEQ * DMODEL];   // V^T per head [b,h][dh][s']

// ---- helpers ---------------------------------------------------------------
__device__ __forceinline__ void mma16(float* c, const unsigned* a, unsigned b0, unsigned b1) {
    asm volatile(
        "mma.sync.aligned.m16n8k16.row.col.f32.f16.f16.f32 "
        "{%0,%1,%2,%3}, {%4,%5,%6,%7}, {%8,%9}, {%0,%1,%2,%3};"
        : "+f"(c[0]), "+f"(c[1]), "+f"(c[2]), "+f"(c[3])
        : "r"(a[0]), "r"(a[1]), "r"(a[2]), "r"(a[3]), "r"(b0), "r"(b1));
}
__device__ __forceinline__ void ldsm4(unsigned r[4], unsigned addr) {
    asm volatile("ldmatrix.sync.aligned.m8n8.x4.shared.b16 {%0,%1,%2,%3}, [%4];"
                 : "=r"(r[0]), "=r"(r[1]), "=r"(r[2]), "=r"(r[3]) : "r"(addr) : "memory");
}
// bare exp2 (argument already in log2 domain via Q pre-scale)
__device__ __forceinline__ float ex2f(float x) {
    float r; asm("ex2.approx.f32 %0, %1;" : "=f"(r) : "f"(x)); return r;
}
// pack two fp32 -> one f16x2 register (lo = first arg, hi = second arg)
__device__ __forceinline__ unsigned packh2(float lo, float hi) {
    unsigned r;
    asm("cvt.rn.f16x2.f32 %0, %1, %2;" : "=r"(r) : "f"(hi), "f"(lo));
    return r;
}
// streaming (evict-first) float2 store — sim/out are write-once
__device__ __forceinline__ void stg_cs2(float* p, float x, float y) {
    asm volatile("st.global.cs.v2.f32 [%0], {%1, %2};" :: "l"(p), "f"(x), "f"(y));
}
__device__ __forceinline__ unsigned s2u(const void* p) {
    return (unsigned)__cvta_generic_to_shared(p);
}
__device__ __forceinline__ void cpa16(unsigned dst, const void* src) {
    asm volatile("cp.async.cg.shared.global [%0], [%1], 16;" :: "r"(dst), "l"(src));
}
#define CP_COMMIT() asm volatile("cp.async.commit_group;")
#define CP_WAIT0()  asm volatile("cp.async.wait_group 0;")
#define CP_WAIT1()  asm volatile("cp.async.wait_group 1;")
#define CP_WAIT2()  asm volatile("cp.async.wait_group 2;")

// XOR swizzle for [*, 64] f16 tiles (half index); 16B groups of 8 halves
__device__ __forceinline__ int offh(int r, int grp) { return r * 64 + ((grp ^ (r & 7)) << 3); }

// fp16 A-fragment (16x16) LDSM address (k16 = 0,16,32,48)
__device__ __forceinline__ unsigned afrag16_addr(unsigned base, int lane, int row16, int k16) {
    const int m = lane >> 3, r = lane & 7;
    const int row = row16 + r + ((m & 1) << 3);
    const int grp = (k16 >> 3) + (m >> 1);
    return base + 2u * (unsigned)offh(row, grp);
}
// fp16 B-fragment pair (n-blocks ntp*16, ntp*16+8 at k16-chunk ks)
__device__ __forceinline__ unsigned bfrag16_addr(unsigned base, int lane, int ntp, int ks) {
    const int m = lane >> 3, r = lane & 7;
    const int row = (ntp << 4) + ((m >> 1) << 3) + r;
    const int grp = (ks << 1) + (m & 1);
    return base + 2u * (unsigned)offh(row, grp);
}

// cp.async of f16 tiles (rows x 64 halves), offh-swizzled, strided gmem
__device__ __forceinline__ void cp_htile128(unsigned sbase, const __half* g, int ldg, int tid) {
    #pragma unroll
    for (int it = 0; it < 4; it++) {
        int i = tid + it * 256, r = i >> 3, gq = i & 7;
        cpa16(sbase + 2u * (unsigned)offh(r, gq), g + (size_t)r * ldg + gq * 8);
    }
}
__device__ __forceinline__ void cp_htile64(unsigned sbase, const __half* g, int ldg, int tid) {
    #pragma unroll
    for (int it = 0; it < 2; it++) {
        int i = tid + it * 256, r = i >> 3, gq = i & 7;
        cpa16(sbase + 2u * (unsigned)offh(r, gq), g + (size_t)r * ldg + gq * 8);
    }
}

// ---------------------------------------------------------------------------
// One-shot fp16 conversion of X and the three weight matrices.
// ---------------------------------------------------------------------------
__global__ void __launch_bounds__(256) cvt_kernel(
    const float4* __restrict__ X,  const float4* __restrict__ Wq,
    const float4* __restrict__ Wk, const float4* __restrict__ Wv)
{
    const int i = blockIdx.x * 256 + threadIdx.x;
    const float4* src; __half* dst; int j;
    if (i < 1048576)      { src = X;  dst = g_X;  j = i; }
    else if (i < 1310720) { src = Wq; dst = g_Wq; j = i - 1048576; }
    else if (i < 1572864) { src = Wk; dst = g_Wk; j = i - 1310720; }
    else                  { src = Wv; dst = g_Wv; j = i - 1572864; }
    float4 v = src[j];
    *(__half2*)(dst + 4 * (size_t)j)     = __floats2half2_rn(v.x, v.y);
    *(__half2*)(dst + 4 * (size_t)j + 2) = __floats2half2_rn(v.z, v.w);
}

// ---------------------------------------------------------------------------
// Projection: Y = X @ W^T, fp16 mma, 3-stage cp.async ring.
// 128x64 tiles, 256 threads. bz==0 -> g_Q (PRE-SCALED by QSCALE);
// bz==1 -> g_K; bz==2 -> fp16 g_Vt^T.
// smem ring: A 3x16KB + B 3x8KB = 72KB dynamic.
// ---------------------------------------------------------------------------
__global__ void __launch_bounds__(256, 2) proj_kernel(int unused)
{
    extern __shared__ char dynC[];
    const unsigned uA[3] = { s2u(dynC),         s2u(dynC + 16384), s2u(dynC + 32768) };
    const unsigned uB[3] = { s2u(dynC + 49152), s2u(dynC + 57344), s2u(dynC + 65536) };

    const int bz = blockIdx.z;
    const __half* __restrict__ W = (bz == 0) ? g_Wq : (bz == 1) ? g_Wk : g_Wv;

    const int rowBase = blockIdx.y * 128;
    const int colBase = blockIdx.x * 64;
    const int tid  = threadIdx.x;
    const int warp = tid >> 5;
    const int lane = tid & 31;

    auto issue = [&](int ki, int slot) {
        const int k0 = ki * 64;
        cp_htile128(uA[slot], g_X + (size_t)rowBase * DMODEL + k0, DMODEL, tid);
        cp_htile64 (uB[slot], W   + (size_t)colBase * DMODEL + k0, DMODEL, tid);
        CP_COMMIT();
    };

    float c[8][4] = {};
    issue(0, 0);
    issue(1, 1);
    for (int ki = 0; ki < 16; ki++) {
        if (ki < 15) { CP_WAIT1(); } else { CP_WAIT0(); }
        __syncthreads();
        if (ki + 2 < 16) issue(ki + 2, (ki + 2) % 3);
        const unsigned ua = uA[ki % 3], ub = uB[ki % 3];
        #pragma unroll
        for (int kc = 0; kc < 4; kc++) {
            unsigned aa[4];
            ldsm4(aa, afrag16_addr(ua, lane, warp * 16, kc * 16));
            #pragma unroll
            for (int ntp = 0; ntp < 4; ntp++) {
                unsigned bb[4];
                ldsm4(bb, bfrag16_addr(ub, lane, ntp, kc));
                mma16(c[2 * ntp],     aa, bb[0], bb[1]);
                mma16(c[2 * ntp + 1], aa, bb[2], bb[3]);
            }
        }
        __syncthreads();
    }

    const int g = lane >> 2, t = lane & 3;
    const int r0 = rowBase + warp * 16 + g;

    if (bz == 0) {
        // Q: fold softmax scale + log2(e) in here
        #pragma unroll
        for (int nt = 0; nt < 8; nt++) {
            const int col = colBase + nt * 8 + 2 * t;
            *(__half2*)(g_Q + (size_t)r0 * DMODEL + col)
                = __floats2half2_rn(c[nt][0] * QSCALE, c[nt][1] * QSCALE);
            *(__half2*)(g_Q + (size_t)(r0 + 8) * DMODEL + col)
                = __floats2half2_rn(c[nt][2] * QSCALE, c[nt][3] * QSCALE);
        }
    } else if (bz == 1) {
        #pragma unroll
        for (int nt = 0; nt < 8; nt++) {
            const int col = colBase + nt * 8 + 2 * t;
            *(__half2*)(g_K + (size_t)r0 * DMODEL + col)       = __floats2half2_rn(c[nt][0], c[nt][1]);
            *(__half2*)(g_K + (size_t)(r0 + 8) * DMODEL + col) = __floats2half2_rn(c[nt][2], c[nt][3]);
        }
    } else {
        // V: scatter fp16 into g_Vt[b,h][dh][s']
        const int b_ = r0 >> 11;
        const int h_ = (r0 >> 7) & 15;
        const int s0 = (r0 & 127) * 16 + (colBase >> 6);
        __half* __restrict__ Vt = g_Vt + (size_t)(b_ * NHEAD + h_) * DHEAD * SEQ;
        #pragma unroll
        for (int nt = 0; nt < 8; nt++) {
            const int d = nt * 8 + 2 * t;
            Vt[(size_t)d * SEQ + s0]             = __float2half_rn(c[nt][0]);
            Vt[(size_t)(d + 1) * SEQ + s0]       = __float2half_rn(c[nt][1]);
            Vt[(size_t)d * SEQ + s0 + 128]       = __float2half_rn(c[nt][2]);
            Vt[(size_t)(d + 1) * SEQ + s0 + 128] = __float2half_rn(c[nt][3]);
        }
    }
}

// ---------------------------------------------------------------------------
// Attention per (b,h). 128-query tile, 256 threads (8 warps x 16 rows).
// Q is pre-scaled so exp(q.k/32) == ex2(logit): bare MUFU, no FMULs.
// Phase 1: fp16 QK^T + ex2 + den accumulation (NO memory writes).
// Phase 2: recompute QK^T, ex2, streaming-write NORMALIZED sim fp32, and
//          PV mma with A-fragments packed straight from the exp registers.
// dynamic smem: sQ 16KB + K ring 3x8KB + V ring 3x8KB = 64KB.
// ---------------------------------------------------------------------------
__global__ void __launch_bounds__(256, 2) attn_kernel(
    float* __restrict__ out_attn,   // [B, S, D]
    float* __restrict__ out_sim)    // [B, H, S, S]
{
    extern __shared__ char dynC[];

    const int qt = blockIdx.x;      // 0..15
    const int h  = blockIdx.y;
    const int b  = blockIdx.z;

    const size_t headOff = ((size_t)b * SEQ + (size_t)h * 128) * DMODEL;
    const __half* __restrict__ Qh  = g_Q + headOff;
    const __half* __restrict__ Kh  = g_K + headOff;
    const __half* __restrict__ VtH = g_Vt + (size_t)(b * NHEAD + h) * DHEAD * SEQ;
    float* __restrict__ simB = out_sim + (size_t)(b * NHEAD + h) * SEQ * SEQ;

    const int tid  = threadIdx.x;
    const int warp = tid >> 5;
    const int lane = tid & 31;
    const int g = lane >> 2, t = lane & 3;

    const int rloc = warp * 16 + g;
    const int qrow = qt * 128 + rloc;

    const unsigned uQ = s2u(dynC);
    const unsigned uKr[3] = { s2u(dynC + 16384), s2u(dynC + 24576), s2u(dynC + 32768) };
    const unsigned uVr[3] = { s2u(dynC + 40960), s2u(dynC + 49152), s2u(dynC + 57344) };

    // ---- Q tile + fragments (kept in registers for both phases) ------------
    cp_htile128(uQ, Qh + (size_t)qt * 128 * DHEAD, DHEAD, tid); CP_COMMIT();
    cp_htile64(uKr[0], Kh,        DHEAD, tid); CP_COMMIT();
    cp_htile64(uKr[1], Kh + 4096, DHEAD, tid); CP_COMMIT();
    CP_WAIT2();                    // Q resident (K0/K1 may still be in flight)
    __syncthreads();

    unsigned qa[4][4];
    #pragma unroll
    for (int kc = 0; kc < 4; kc++)
        ldsm4(qa[kc], afrag16_addr(uQ, lane, warp * 16, kc * 16));

    // ---------------- Phase 1: den only, no writes ----------------
    float den0 = 0.0f, den1 = 0.0f;
    for (int kt = 0; kt < 32; kt++) {
        if (kt < 31) { CP_WAIT1(); } else { CP_WAIT0(); }
        __syncthreads();
        if (kt + 2 < 32) {
            cp_htile64(uKr[(kt + 2) % 3], Kh + (size_t)(kt + 2) * 4096, DHEAD, tid);
            CP_COMMIT();
        }
        const unsigned uk = uKr[kt % 3];

        float c[8][4] = {};
        #pragma unroll
        for (int kc = 0; kc < 4; kc++) {
            #pragma unroll
            for (int ntp = 0; ntp < 4; ntp++) {
                unsigned bb[4];
                ldsm4(bb, bfrag16_addr(uk, lane, ntp, kc));
                mma16(c[2 * ntp],     qa[kc], bb[0], bb[1]);
                mma16(c[2 * ntp + 1], qa[kc], bb[2], bb[3]);
            }
        }
        #pragma unroll
        for (int nt = 0; nt < 8; nt++) {
            den0 += ex2f(c[nt][0]) + ex2f(c[nt][1]);
            den1 += ex2f(c[nt][2]) + ex2f(c[nt][3]);
        }
    }
    #pragma unroll
    for (int o = 1; o < 4; o <<= 1) {
        den0 += __shfl_xor_sync(0xffffffffu, den0, o, 4);
        den1 += __shfl_xor_sync(0xffffffffu, den1, o, 4);
    }
    const float inv0 = 1.0f / den0;
    const float inv1 = 1.0f / den1;

    // ---------------- Phase 2: recompute + sim write + PV ----------------
    float o2[8][4] = {};
    __syncthreads();                  // phase-1 ring reads done

    auto issue_kv = [&](int kt, int slot) {
        cp_htile64(uKr[slot], Kh  + (size_t)kt * 4096, DHEAD, tid);
        cp_htile64(uVr[slot], VtH + kt * 64,           SEQ,   tid);
        CP_COMMIT();
    };
    issue_kv(0, 0);
    issue_kv(1, 1);

    for (int kt = 0; kt < 32; kt++) {
        if (kt < 31) { CP_WAIT1(); } else { CP_WAIT0(); }
        __syncthreads();
        if (kt + 2 < 32) issue_kv(kt + 2, (kt + 2) % 3);

        const unsigned uk = uKr[kt % 3], uv = uVr[kt % 3];

        // QK^T recompute
        float c[8][4] = {};
        #pragma unroll
        for (int kc = 0; kc < 4; kc++) {
            #pragma unroll
            for (int ntp = 0; ntp < 4; ntp++) {
                unsigned bb[4];
                ldsm4(bb, bfrag16_addr(uk, lane, ntp, kc));
                mma16(c[2 * ntp],     qa[kc], bb[0], bb[1]);
                mma16(c[2 * ntp + 1], qa[kc], bb[2], bb[3]);
            }
        }

        // ex2; streaming-write normalized sim; keep raw exp in c for PV
        #pragma unroll
        for (int nt = 0; nt < 8; nt++) {
            float e0 = ex2f(c[nt][0]);
            float e1 = ex2f(c[nt][1]);
            float e2 = ex2f(c[nt][2]);
            float e3 = ex2f(c[nt][3]);
            const int col = kt * 64 + nt * 8 + 2 * t;
            stg_cs2(simB + (size_t)qrow * SEQ + col,       e0 * inv0, e1 * inv0);
            stg_cs2(simB + (size_t)(qrow + 8) * SEQ + col, e2 * inv1, e3 * inv1);
            c[nt][0] = e0; c[nt][1] = e1; c[nt][2] = e2; c[nt][3] = e3;
        }

        // PV: A-frags packed directly from exp registers (no smem, no shuffle)
        #pragma unroll
        for (int kc = 0; kc < 4; kc++) {
            unsigned aa[4];
            aa[0] = packh2(c[2 * kc][0],     c[2 * kc][1]);
            aa[1] = packh2(c[2 * kc][2],     c[2 * kc][3]);
            aa[2] = packh2(c[2 * kc + 1][0], c[2 * kc + 1][1]);
            aa[3] = packh2(c[2 * kc + 1][2], c[2 * kc + 1][3]);
            #pragma unroll
            for (int ntp = 0; ntp < 4; ntp++) {
                unsigned bb[4];
                ldsm4(bb, bfrag16_addr(uv, lane, ntp, kc));
                mma16(o2[2 * ntp],     aa, bb[0], bb[1]);
                mma16(o2[2 * ntp + 1], aa, bb[2], bb[3]);
            }
        }
    }

    // Write self_attn with the (0,2,1,3) head transpose; scale by inv here.
    #pragma unroll
    for (int nt = 0; nt < 8; nt++) {
        const int dh = h * DHEAD + nt * 8 + 2 * t;
        stg_cs2(out_attn + ((size_t)b * SEQ + qrow) * DMODEL + dh,
                o2[nt][0] * inv0, o2[nt][1] * inv0);
        stg_cs2(out_attn + ((size_t)b * SEQ + qrow + 8) * DMODEL + dh,
                o2[nt][2] * inv1, o2[nt][3] * inv1);
    }
}

// ---------------------------------------------------------------------------
extern "C" void kernel_launch(void* const* d_in, const int* in_sizes, int n_in,
                              void* d_out, int out_size)
{
    const float* seq = (const float*)d_in[0];
    const float* Wq  = (const float*)d_in[1];
    const float* Wk  = (const float*)d_in[2];
    const float* Wv  = (const float*)d_in[3];

    float* out_attn = (float*)d_out;
    float* out_sim  = (float*)d_out + (size_t)BATCH * SEQ * DMODEL;

    static int attr_set = 0;
    if (!attr_set) {
        cudaFuncSetAttribute(proj_kernel, cudaFuncAttributeMaxDynamicSharedMemorySize, 80 * 1024);
        cudaFuncSetAttribute(attn_kernel, cudaFuncAttributeMaxDynamicSharedMemorySize, 64 * 1024);
        attr_set = 1;
    }

    cvt_kernel<<<7168, 256>>>((const float4*)seq, (const float4*)Wq,
                              (const float4*)Wk,  (const float4*)Wv);
    proj_kernel<<<dim3(DMODEL / 64, (BATCH * SEQ) / 128, 3), 256, 72 * 1024>>>(0);
    attn_kernel<<<dim3(SEQ / 128, NHEAD, BATCH), 256, 64 * 1024>>>(out_attn, out_sim);
}